// round 12
// baseline (speedup 1.0000x reference)
#include <cuda_runtime.h>
#include <cuda_bf16.h>
#include <cstdint>

#define NN 100000
#define EE 500000
#define BB 4096
#define HC 128
#define NH 4
#define HID 32
#define EDIM 4

#define SCAN_T 512
#define SCAN_B ((NN + SCAN_T - 1) / SCAN_T)  // 196

// ---------------- scratch (device globals: allocation-free) ----------------
__device__ float         g_q[NN * HC];
__device__ __nv_bfloat16 g_kvb[NN * HC * 2];  // interleaved [n][c][{k,v}] bf16
__device__ float         g_s[NN * HC];        // skip (x@Ws + bs)
__device__ float         g_h[NN * HC];        // layer output / next-layer input
__device__ float         g_pooled[BB * HC];
__device__ float         g_cnt[BB];
// CSR build
__device__ int    g_deg[NN];
__device__ int    g_incl[NN];
__device__ int    g_rowptr[NN + 1];
__device__ int    g_cursor[NN];
__device__ int    g_bsum[SCAN_B];
__device__ int    g_boff[SCAN_B];
__device__ int    g_esrc[EE];
__device__ float4 g_eea[EE];

// ---------------- side stream for overlap ----------------
static cudaStream_t g_s2;
static cudaEvent_t g_evA, g_evB;
namespace {
struct StreamInit {
    StreamInit() {
        cudaStreamCreateWithFlags(&g_s2, cudaStreamNonBlocking);
        cudaEventCreateWithFlags(&g_evA, cudaEventDisableTiming);
        cudaEventCreateWithFlags(&g_evB, cudaEventDisableTiming);
    }
} g_stream_init;
}

// ---------------- helpers ----------------
__device__ __forceinline__ float to_tf32(float x) {
    uint32_t u;
    asm("cvt.rna.tf32.f32 %0, %1;" : "=r"(u) : "f"(x));
    return __uint_as_float(u);
}

__device__ __forceinline__ void mma_tf32(float& c0, float& c1, float& c2, float& c3,
                                         uint32_t a0, uint32_t a1, uint32_t a2, uint32_t a3,
                                         uint32_t b0, uint32_t b1) {
    asm volatile(
        "mma.sync.aligned.m16n8k8.row.col.f32.tf32.tf32.f32 "
        "{%0,%1,%2,%3}, {%4,%5,%6,%7}, {%8,%9}, {%0,%1,%2,%3};"
        : "+f"(c0), "+f"(c1), "+f"(c2), "+f"(c3)
        : "r"(a0), "r"(a1), "r"(a2), "r"(a3), "r"(b0), "r"(b1));
}

// ---------------- CSR build ----------------
__global__ void zero_deg_kernel() {
    int stride = gridDim.x * blockDim.x;
    for (int i = blockIdx.x * blockDim.x + threadIdx.x; i < NN; i += stride) g_deg[i] = 0;
}

__global__ void hist_kernel(const int* __restrict__ ei) {
    int stride = gridDim.x * blockDim.x;
    for (int e = blockIdx.x * blockDim.x + threadIdx.x; e < EE; e += stride)
        atomicAdd(&g_deg[ei[EE + e]], 1);
}

__global__ void scanA_kernel() {
    __shared__ int s[SCAN_T];
    int tid = threadIdx.x;
    int i = blockIdx.x * SCAN_T + tid;
    int v = (i < NN) ? g_deg[i] : 0;
    s[tid] = v;
    __syncthreads();
#pragma unroll
    for (int off = 1; off < SCAN_T; off <<= 1) {
        int t = (tid >= off) ? s[tid - off] : 0;
        __syncthreads();
        s[tid] += t;
        __syncthreads();
    }
    if (i < NN) g_incl[i] = s[tid];
    if (tid == SCAN_T - 1) g_bsum[blockIdx.x] = s[tid];
}

__global__ void scanB_kernel() {
    __shared__ int s[256];
    int tid = threadIdx.x;
    int v = (tid < SCAN_B) ? g_bsum[tid] : 0;
    s[tid] = v;
    __syncthreads();
#pragma unroll
    for (int off = 1; off < 256; off <<= 1) {
        int t = (tid >= off) ? s[tid - off] : 0;
        __syncthreads();
        s[tid] += t;
        __syncthreads();
    }
    if (tid < SCAN_B) g_boff[tid] = s[tid] - v;
}

__global__ void scanC_kernel() {
    int i = blockIdx.x * SCAN_T + threadIdx.x;
    if (i < NN) {
        int excl = g_incl[i] - g_deg[i] + g_boff[blockIdx.x];
        g_rowptr[i] = excl;
        g_cursor[i] = excl;
    }
    if (i == 0) g_rowptr[NN] = EE;
}

__global__ void bucket_kernel(const int* __restrict__ ei, const float* __restrict__ ea) {
    int stride = gridDim.x * blockDim.x;
    for (int e = blockIdx.x * blockDim.x + threadIdx.x; e < EE; e += stride) {
        int dst = ei[EE + e];
        int pos = atomicAdd(&g_cursor[dst], 1);
        g_esrc[pos] = ei[e];
        g_eea[pos] = reinterpret_cast<const float4*>(ea)[e];
    }
}

// ---------------- zero pool + count ----------------
__global__ void zero_pool_kernel() {
    int stride = gridDim.x * blockDim.x;
    int i0 = blockIdx.x * blockDim.x + threadIdx.x;
    for (int i = i0; i < BB * HC; i += stride) g_pooled[i] = 0.f;
    for (int i = i0; i < BB; i += stride) g_cnt[i] = 0.f;
}

__global__ void cnt_kernel(const int* __restrict__ batch) {
    int n = blockIdx.x * blockDim.x + threadIdx.x;
    if (n < NN) atomicAdd(&g_cnt[batch[n]], 1.f);
}

// ---------------- split tensor-core GEMM (R7 structure) ----------------
// One matrix per block (blockIdx.y), 64x128 tile, warp tile 32x32,
// register-prefetch double buffering. k and v epilogues write interleaved bf16.
template <int D, bool USE_H>
__global__ __launch_bounds__(256, 2) void gemm_tc_kernel(
    const float* __restrict__ x,
    const float* __restrict__ Wq, const float* __restrict__ bq,
    const float* __restrict__ Wk, const float* __restrict__ bk,
    const float* __restrict__ Wv, const float* __restrict__ bv,
    const float* __restrict__ Ws, const float* __restrict__ bs) {
    __shared__ __align__(16) float xs[64][36];
    __shared__ __align__(16) float ws[32][136];

    const float* xin = USE_H ? g_h : x;
    const float* W;
    const float* bias;
    int m = blockIdx.y;
    if (m == 0)      { W = Wq; bias = bq; }
    else if (m == 1) { W = Wk; bias = bk; }
    else if (m == 2) { W = Wv; bias = bv; }
    else             { W = Ws; bias = bs; }

    int node0 = blockIdx.x * 64;
    int tid = threadIdx.x;
    int lane = tid & 31, wid = tid >> 5;
    int warp_m = wid >> 2, warp_n = wid & 3;  // 2 x 4, warp tile 32x32
    int gID = lane >> 2, t4 = lane & 3;

    const int xr_r[2] = {(tid + 0) >> 3, (tid + 256) >> 3};
    const int xr_c = (tid & 7) * 4;
    const int wr_r[4] = {(tid + 0) >> 5, (tid + 256) >> 5, (tid + 512) >> 5, (tid + 768) >> 5};
    const int wr_c = (tid & 31) * 4;

    float4 xr[2], wr[4];
    auto load_chunk = [&](int k0) {
#pragma unroll
        for (int t = 0; t < 2; t++) {
            int n = node0 + xr_r[t];
            xr[t] = (n < NN) ? *(const float4*)&xin[n * D + k0 + xr_c]
                             : make_float4(0.f, 0.f, 0.f, 0.f);
        }
#pragma unroll
        for (int t = 0; t < 4; t++)
            wr[t] = *(const float4*)&W[(k0 + wr_r[t]) * HC + wr_c];
    };
    auto store_chunk = [&]() {
#pragma unroll
        for (int t = 0; t < 2; t++) {
            float* xp = &xs[xr_r[t]][xr_c];
            xp[0] = to_tf32(xr[t].x); xp[1] = to_tf32(xr[t].y);
            xp[2] = to_tf32(xr[t].z); xp[3] = to_tf32(xr[t].w);
        }
#pragma unroll
        for (int t = 0; t < 4; t++) {
            float* wp = &ws[wr_r[t]][wr_c];
            wp[0] = to_tf32(wr[t].x); wp[1] = to_tf32(wr[t].y);
            wp[2] = to_tf32(wr[t].z); wp[3] = to_tf32(wr[t].w);
        }
    };

    float acc[2][4][4];
#pragma unroll
    for (int mi = 0; mi < 2; mi++)
#pragma unroll
        for (int ni = 0; ni < 4; ni++)
#pragma unroll
            for (int r = 0; r < 4; r++) acc[mi][ni][r] = 0.f;

    load_chunk(0);
#pragma unroll
    for (int k0 = 0; k0 < D; k0 += 32) {
        store_chunk();
        __syncthreads();
        if (k0 + 32 < D) load_chunk(k0 + 32);  // prefetch overlaps mma below

#pragma unroll
        for (int ks = 0; ks < 4; ks++) {
            int kk = ks * 8;
            uint32_t a[2][4], bf[4][2];
#pragma unroll
            for (int mi = 0; mi < 2; mi++) {
                int row = warp_m * 32 + mi * 16 + gID;
                a[mi][0] = __float_as_uint(xs[row][kk + t4]);
                a[mi][1] = __float_as_uint(xs[row + 8][kk + t4]);
                a[mi][2] = __float_as_uint(xs[row][kk + t4 + 4]);
                a[mi][3] = __float_as_uint(xs[row + 8][kk + t4 + 4]);
            }
#pragma unroll
            for (int ni = 0; ni < 4; ni++) {
                int col = warp_n * 32 + ni * 8 + gID;
                bf[ni][0] = __float_as_uint(ws[kk + t4][col]);
                bf[ni][1] = __float_as_uint(ws[kk + t4 + 4][col]);
            }
#pragma unroll
            for (int mi = 0; mi < 2; mi++)
#pragma unroll
                for (int ni = 0; ni < 4; ni++)
                    mma_tf32(acc[mi][ni][0], acc[mi][ni][1], acc[mi][ni][2], acc[mi][ni][3],
                             a[mi][0], a[mi][1], a[mi][2], a[mi][3],
                             bf[ni][0], bf[ni][1]);
        }
        __syncthreads();
    }

#pragma unroll
    for (int mi = 0; mi < 2; mi++) {
        int r0 = node0 + warp_m * 32 + mi * 16 + gID;
#pragma unroll
        for (int ni = 0; ni < 4; ni++) {
            int cb = warp_n * 32 + ni * 8 + 2 * t4;
            float b0v = bias[cb], b1v = bias[cb + 1];
            float v00 = acc[mi][ni][0] + b0v, v01 = acc[mi][ni][1] + b1v;
            float v10 = acc[mi][ni][2] + b0v, v11 = acc[mi][ni][3] + b1v;
            if (m == 0) {
                if (r0 < NN)     { g_q[r0 * HC + cb] = v00; g_q[r0 * HC + cb + 1] = v01; }
                if (r0 + 8 < NN) { g_q[(r0 + 8) * HC + cb] = v10; g_q[(r0 + 8) * HC + cb + 1] = v11; }
            } else if (m == 3) {
                if (r0 < NN)     { g_s[r0 * HC + cb] = v00; g_s[r0 * HC + cb + 1] = v01; }
                if (r0 + 8 < NN) { g_s[(r0 + 8) * HC + cb] = v10; g_s[(r0 + 8) * HC + cb + 1] = v11; }
            } else {
                int off = (m == 1) ? 0 : 1;  // k at [0], v at [1]
                if (r0 < NN) {
                    g_kvb[2 * (r0 * HC + cb) + off]     = __float2bfloat16(v00);
                    g_kvb[2 * (r0 * HC + cb + 1) + off] = __float2bfloat16(v01);
                }
                if (r0 + 8 < NN) {
                    g_kvb[2 * ((r0 + 8) * HC + cb) + off]     = __float2bfloat16(v10);
                    g_kvb[2 * ((r0 + 8) * HC + cb + 1) + off] = __float2bfloat16(v11);
                }
            }
        }
    }
}

// ---------------- per-node fused edge pass (gather, no atomics) ----------------
// One warp per destination node; 2-way edge unroll; single bf16x2 gather per
// lane per head delivers both k and v (512B/edge vs 1024B fp32).
template <bool RELU, bool POOL>
__global__ __launch_bounds__(256) void node_edge_kernel(const float* __restrict__ We,
                                                        const int* __restrict__ batch) {
    __shared__ float Wes[EDIM * HC];
    for (int i = threadIdx.x; i < EDIM * HC; i += blockDim.x) Wes[i] = We[i];
    __syncthreads();

    int n = blockIdx.x * 8 + (threadIdx.x >> 5);
    int lane = threadIdx.x & 31;
    if (n >= NN) return;

    int r0 = g_rowptr[n];
    int r1 = g_rowptr[n + 1];

    float qv[NH], acc[NH], asum[NH];
#pragma unroll
    for (int j = 0; j < NH; j++) {
        qv[j] = g_q[n * HC + j * HID + lane];
        acc[j] = 0.f;
        asum[j] = 0.f;
    }

    int i = r0;
    for (; i + 1 < r1; i += 2) {
        int s0 = g_esrc[i], s1 = g_esrc[i + 1];
        float4 a0 = g_eea[i], a1 = g_eea[i + 1];
        float k0[NH], v0[NH], k1[NH], v1[NH];
#pragma unroll
        for (int j = 0; j < NH; j++) {
            int c = j * HID + lane;
            __nv_bfloat162 kv0 = *reinterpret_cast<const __nv_bfloat162*>(&g_kvb[2 * (s0 * HC + c)]);
            __nv_bfloat162 kv1 = *reinterpret_cast<const __nv_bfloat162*>(&g_kvb[2 * (s1 * HC + c)]);
            k0[j] = __bfloat162float(kv0.x); v0[j] = __bfloat162float(kv0.y);
            k1[j] = __bfloat162float(kv1.x); v1[j] = __bfloat162float(kv1.y);
        }
        float e0[NH], e1[NH], p0[NH], p1[NH];
#pragma unroll
        for (int j = 0; j < NH; j++) {
            int c = j * HID + lane;
            float w0 = Wes[c], w1 = Wes[HC + c], w2 = Wes[2 * HC + c], w3 = Wes[3 * HC + c];
            e0[j] = a0.x * w0 + a0.y * w1 + a0.z * w2 + a0.w * w3;
            e1[j] = a1.x * w0 + a1.y * w1 + a1.z * w2 + a1.w * w3;
            p0[j] = qv[j] * (k0[j] + e0[j]);
            p1[j] = qv[j] * (k1[j] + e1[j]);
        }
#pragma unroll
        for (int off = 16; off; off >>= 1) {
#pragma unroll
            for (int j = 0; j < NH; j++) {
                p0[j] += __shfl_xor_sync(0xffffffffu, p0[j], off);
                p1[j] += __shfl_xor_sync(0xffffffffu, p1[j], off);
            }
        }
#pragma unroll
        for (int j = 0; j < NH; j++) {
            float al0 = __expf(p0[j] * 0.17677669529663687f);
            float al1 = __expf(p1[j] * 0.17677669529663687f);
            asum[j] += al0 + al1;
            acc[j] = fmaf(v0[j] + e0[j], al0, acc[j]);
            acc[j] = fmaf(v1[j] + e1[j], al1, acc[j]);
        }
    }
    if (i < r1) {
        int s0 = g_esrc[i];
        float4 a0 = g_eea[i];
        float k0[NH], v0[NH], e0[NH], p0[NH];
#pragma unroll
        for (int j = 0; j < NH; j++) {
            int c = j * HID + lane;
            __nv_bfloat162 kv0 = *reinterpret_cast<const __nv_bfloat162*>(&g_kvb[2 * (s0 * HC + c)]);
            k0[j] = __bfloat162float(kv0.x); v0[j] = __bfloat162float(kv0.y);
        }
#pragma unroll
        for (int j = 0; j < NH; j++) {
            int c = j * HID + lane;
            e0[j] = a0.x * Wes[c] + a0.y * Wes[HC + c] + a0.z * Wes[2 * HC + c] + a0.w * Wes[3 * HC + c];
            p0[j] = qv[j] * (k0[j] + e0[j]);
        }
#pragma unroll
        for (int j = 0; j < NH; j++) {
#pragma unroll
            for (int off = 16; off; off >>= 1) p0[j] += __shfl_xor_sync(0xffffffffu, p0[j], off);
        }
#pragma unroll
        for (int j = 0; j < NH; j++) {
            float al = __expf(p0[j] * 0.17677669529663687f);
            asum[j] += al;
            acc[j] = fmaf(v0[j] + e0[j], al, acc[j]);
        }
    }

    int bslot = POOL ? batch[n] : 0;
#pragma unroll
    for (int j = 0; j < NH; j++) {
        int c = j * HID + lane;
        float h = acc[j] / (asum[j] + 1e-16f) + g_s[n * HC + c];
        if (RELU) h = fmaxf(h, 0.f);
        if (POOL) atomicAdd(&g_pooled[bslot * HC + c], h);
        else g_h[n * HC + c] = h;
    }
}

// ---------------- head ----------------
__global__ void head_kernel(const int* __restrict__ rt,
                            const float* __restrict__ hW,
                            const float* __restrict__ hb,
                            float* __restrict__ out) {
    int b = (blockIdx.x * blockDim.x + threadIdx.x) >> 5;
    int lane = threadIdx.x & 31;
    if (b >= BB) return;
    int r = rt[b];
    float acc = 0.f;
#pragma unroll
    for (int j = 0; j < NH; j++) {
        int c = j * HID + lane;
        acc = fmaf(g_pooled[b * HC + c], hW[r * HC + c], acc);
    }
#pragma unroll
    for (int off = 16; off; off >>= 1) acc += __shfl_xor_sync(0xffffffffu, acc, off);
    if (lane == 0) {
        float cnt = fmaxf(g_cnt[b], 1.f);
        out[b] = acc / cnt + hb[r];
    }
}

// ---------------- launch ----------------
extern "C" void kernel_launch(void* const* d_in, const int* in_sizes, int n_in,
                              void* d_out, int out_size) {
    const float* x     = (const float*)d_in[0];
    const int*   ei    = (const int*)d_in[1];
    const float* ea    = (const float*)d_in[2];
    const int*   batch = (const int*)d_in[3];
    const int*   rt    = (const int*)d_in[4];
    const float* Wq1 = (const float*)d_in[5];
    const float* bq1 = (const float*)d_in[6];
    const float* Wk1 = (const float*)d_in[7];
    const float* bk1 = (const float*)d_in[8];
    const float* Wv1 = (const float*)d_in[9];
    const float* bv1 = (const float*)d_in[10];
    const float* We1 = (const float*)d_in[11];
    const float* Ws1 = (const float*)d_in[12];
    const float* bs1 = (const float*)d_in[13];
    const float* Wq23 = (const float*)d_in[14];
    const float* bq23 = (const float*)d_in[15];
    const float* Wk23 = (const float*)d_in[16];
    const float* bk23 = (const float*)d_in[17];
    const float* Wv23 = (const float*)d_in[18];
    const float* bv23 = (const float*)d_in[19];
    const float* We23 = (const float*)d_in[20];
    const float* Ws23 = (const float*)d_in[21];
    const float* bs23 = (const float*)d_in[22];
    const float* headW = (const float*)d_in[23];
    const float* headb = (const float*)d_in[24];
    float* out = (float*)d_out;

    const dim3 gemm_grid((NN + 63) / 64, 4);
    const int node_blocks = (NN + 7) / 8;

    // ---- fork: first part of CSR build on side stream ----
    cudaEventRecord(g_evA, 0);
    cudaStreamWaitEvent(g_s2, g_evA, 0);
    zero_deg_kernel<<<256, 256, 0, g_s2>>>();       // kernel 1
    hist_kernel<<<1024, 256, 0, g_s2>>>(ei);        // kernel 2
    scanA_kernel<<<SCAN_B, SCAN_T, 0, g_s2>>>();    // kernel 3

    // ---- main stream: layer-1 GEMM enqueued 4th (profiled slot) ----
    gemm_tc_kernel<64, false><<<gemm_grid, 256>>>(x, Wq1, bq1, Wk1, bk1, Wv1, bv1, Ws1, bs1);

    // ---- rest of side-stream chain ----
    scanB_kernel<<<1, 256, 0, g_s2>>>();
    scanC_kernel<<<SCAN_B, SCAN_T, 0, g_s2>>>();
    bucket_kernel<<<1024, 256, 0, g_s2>>>(ei, ea);
    zero_pool_kernel<<<256, 256, 0, g_s2>>>();
    cnt_kernel<<<(NN + 255) / 256, 256, 0, g_s2>>>(batch);
    cudaEventRecord(g_evB, g_s2);

    cudaStreamWaitEvent(0, g_evB, 0);  // join before first edge pass
    node_edge_kernel<true, false><<<node_blocks, 256>>>(We1, batch);

    gemm_tc_kernel<128, true><<<gemm_grid, 256>>>(
        x, Wq23, bq23, Wk23, bk23, Wv23, bv23, Ws23, bs23);
    node_edge_kernel<true, false><<<node_blocks, 256>>>(We23, batch);

    gemm_tc_kernel<128, true><<<gemm_grid, 256>>>(
        x, Wq23 + HC * HC, bq23 + HC, Wk23 + HC * HC, bk23 + HC,
        Wv23 + HC * HC, bv23 + HC, Ws23 + HC * HC, bs23 + HC);
    node_edge_kernel<false, true><<<node_blocks, 256>>>(We23 + EDIM * HC, batch);

    head_kernel<<<(BB * 32 + 255) / 256, 256>>>(rt, headW, headb, out);
}

// round 13
// speedup vs baseline: 1.5201x; 1.5201x over previous
#include <cuda_runtime.h>
#include <cuda_bf16.h>
#include <cstdint>

#define NN 100000
#define EE 500000
#define BB 4096
#define HC 128
#define NH 4
#define HID 32
#define EDIM 4

#define SCAN_T 512
#define SCAN_B ((NN + SCAN_T - 1) / SCAN_T)  // 196

// ---------------- scratch (device globals: allocation-free) ----------------
__device__ float         g_q[NN * HC];
__device__ __nv_bfloat16 g_kb[NN * HC];   // k bf16 (separate -> packed 32-bit epilogue stores)
__device__ __nv_bfloat16 g_vb[NN * HC];   // v bf16
__device__ float         g_s[NN * HC];    // skip (x@Ws + bs)
__device__ float         g_h[NN * HC];    // layer output / next-layer input
__device__ float         g_pooled[BB * HC];
__device__ float         g_cnt[BB];
// CSR build
__device__ int    g_deg[NN];
__device__ int    g_incl[NN];
__device__ int    g_rowptr[NN + 1];
__device__ int    g_cursor[NN];
__device__ int    g_bsum[SCAN_B];
__device__ int    g_boff[SCAN_B];
__device__ int    g_esrc[EE];
__device__ float4 g_eea[EE];

// ---------------- side stream for overlap ----------------
static cudaStream_t g_s2;
static cudaEvent_t g_evA, g_evB;
namespace {
struct StreamInit {
    StreamInit() {
        cudaStreamCreateWithFlags(&g_s2, cudaStreamNonBlocking);
        cudaEventCreateWithFlags(&g_evA, cudaEventDisableTiming);
        cudaEventCreateWithFlags(&g_evB, cudaEventDisableTiming);
    }
} g_stream_init;
}

// ---------------- helpers ----------------
__device__ __forceinline__ float to_tf32(float x) {
    uint32_t u;
    asm("cvt.rna.tf32.f32 %0, %1;" : "=r"(u) : "f"(x));
    return __uint_as_float(u);
}

__device__ __forceinline__ void mma_tf32(float& c0, float& c1, float& c2, float& c3,
                                         uint32_t a0, uint32_t a1, uint32_t a2, uint32_t a3,
                                         uint32_t b0, uint32_t b1) {
    asm volatile(
        "mma.sync.aligned.m16n8k8.row.col.f32.tf32.tf32.f32 "
        "{%0,%1,%2,%3}, {%4,%5,%6,%7}, {%8,%9}, {%0,%1,%2,%3};"
        : "+f"(c0), "+f"(c1), "+f"(c2), "+f"(c3)
        : "r"(a0), "r"(a1), "r"(a2), "r"(a3), "r"(b0), "r"(b1));
}

// ---------------- CSR build ----------------
__global__ void zero_deg_kernel() {
    int stride = gridDim.x * blockDim.x;
    for (int i = blockIdx.x * blockDim.x + threadIdx.x; i < NN; i += stride) g_deg[i] = 0;
}

__global__ void hist_kernel(const int* __restrict__ ei) {
    int stride = gridDim.x * blockDim.x;
    for (int e = blockIdx.x * blockDim.x + threadIdx.x; e < EE; e += stride)
        atomicAdd(&g_deg[ei[EE + e]], 1);
}

__global__ void scanA_kernel() {
    __shared__ int s[SCAN_T];
    int tid = threadIdx.x;
    int i = blockIdx.x * SCAN_T + tid;
    int v = (i < NN) ? g_deg[i] : 0;
    s[tid] = v;
    __syncthreads();
#pragma unroll
    for (int off = 1; off < SCAN_T; off <<= 1) {
        int t = (tid >= off) ? s[tid - off] : 0;
        __syncthreads();
        s[tid] += t;
        __syncthreads();
    }
    if (i < NN) g_incl[i] = s[tid];
    if (tid == SCAN_T - 1) g_bsum[blockIdx.x] = s[tid];
}

__global__ void scanB_kernel() {
    __shared__ int s[256];
    int tid = threadIdx.x;
    int v = (tid < SCAN_B) ? g_bsum[tid] : 0;
    s[tid] = v;
    __syncthreads();
#pragma unroll
    for (int off = 1; off < 256; off <<= 1) {
        int t = (tid >= off) ? s[tid - off] : 0;
        __syncthreads();
        s[tid] += t;
        __syncthreads();
    }
    if (tid < SCAN_B) g_boff[tid] = s[tid] - v;
}

__global__ void scanC_kernel() {
    int i = blockIdx.x * SCAN_T + threadIdx.x;
    if (i < NN) {
        int excl = g_incl[i] - g_deg[i] + g_boff[blockIdx.x];
        g_rowptr[i] = excl;
        g_cursor[i] = excl;
    }
    if (i == 0) g_rowptr[NN] = EE;
}

__global__ void bucket_kernel(const int* __restrict__ ei, const float* __restrict__ ea) {
    int stride = gridDim.x * blockDim.x;
    for (int e = blockIdx.x * blockDim.x + threadIdx.x; e < EE; e += stride) {
        int dst = ei[EE + e];
        int pos = atomicAdd(&g_cursor[dst], 1);
        g_esrc[pos] = ei[e];
        g_eea[pos] = reinterpret_cast<const float4*>(ea)[e];
    }
}

// ---------------- zero pool + count ----------------
__global__ void zero_pool_kernel() {
    int stride = gridDim.x * blockDim.x;
    int i0 = blockIdx.x * blockDim.x + threadIdx.x;
    for (int i = i0; i < BB * HC; i += stride) g_pooled[i] = 0.f;
    for (int i = i0; i < BB; i += stride) g_cnt[i] = 0.f;
}

__global__ void cnt_kernel(const int* __restrict__ batch) {
    int n = blockIdx.x * blockDim.x + threadIdx.x;
    if (n < NN) atomicAdd(&g_cnt[batch[n]], 1.f);
}

// ---------------- split tensor-core GEMM (R7 structure) ----------------
// One matrix per block (blockIdx.y), 64x128 tile, warp tile 32x32,
// register-prefetch double buffering. k and v epilogues write bf16x2 packed
// 32-bit stores to separate arrays (coalesced, half the fp32 store bytes).
template <int D, bool USE_H>
__global__ __launch_bounds__(256, 2) void gemm_tc_kernel(
    const float* __restrict__ x,
    const float* __restrict__ Wq, const float* __restrict__ bq,
    const float* __restrict__ Wk, const float* __restrict__ bk,
    const float* __restrict__ Wv, const float* __restrict__ bv,
    const float* __restrict__ Ws, const float* __restrict__ bs) {
    __shared__ __align__(16) float xs[64][36];
    __shared__ __align__(16) float ws[32][136];

    const float* xin = USE_H ? g_h : x;
    const float* W;
    const float* bias;
    int m = blockIdx.y;
    if (m == 0)      { W = Wq; bias = bq; }
    else if (m == 1) { W = Wk; bias = bk; }
    else if (m == 2) { W = Wv; bias = bv; }
    else             { W = Ws; bias = bs; }

    int node0 = blockIdx.x * 64;
    int tid = threadIdx.x;
    int lane = tid & 31, wid = tid >> 5;
    int warp_m = wid >> 2, warp_n = wid & 3;  // 2 x 4, warp tile 32x32
    int gID = lane >> 2, t4 = lane & 3;

    const int xr_r[2] = {(tid + 0) >> 3, (tid + 256) >> 3};
    const int xr_c = (tid & 7) * 4;
    const int wr_r[4] = {(tid + 0) >> 5, (tid + 256) >> 5, (tid + 512) >> 5, (tid + 768) >> 5};
    const int wr_c = (tid & 31) * 4;

    float4 xr[2], wr[4];
    auto load_chunk = [&](int k0) {
#pragma unroll
        for (int t = 0; t < 2; t++) {
            int n = node0 + xr_r[t];
            xr[t] = (n < NN) ? *(const float4*)&xin[n * D + k0 + xr_c]
                             : make_float4(0.f, 0.f, 0.f, 0.f);
        }
#pragma unroll
        for (int t = 0; t < 4; t++)
            wr[t] = *(const float4*)&W[(k0 + wr_r[t]) * HC + wr_c];
    };
    auto store_chunk = [&]() {
#pragma unroll
        for (int t = 0; t < 2; t++) {
            float* xp = &xs[xr_r[t]][xr_c];
            xp[0] = to_tf32(xr[t].x); xp[1] = to_tf32(xr[t].y);
            xp[2] = to_tf32(xr[t].z); xp[3] = to_tf32(xr[t].w);
        }
#pragma unroll
        for (int t = 0; t < 4; t++) {
            float* wp = &ws[wr_r[t]][wr_c];
            wp[0] = to_tf32(wr[t].x); wp[1] = to_tf32(wr[t].y);
            wp[2] = to_tf32(wr[t].z); wp[3] = to_tf32(wr[t].w);
        }
    };

    float acc[2][4][4];
#pragma unroll
    for (int mi = 0; mi < 2; mi++)
#pragma unroll
        for (int ni = 0; ni < 4; ni++)
#pragma unroll
            for (int r = 0; r < 4; r++) acc[mi][ni][r] = 0.f;

    load_chunk(0);
#pragma unroll
    for (int k0 = 0; k0 < D; k0 += 32) {
        store_chunk();
        __syncthreads();
        if (k0 + 32 < D) load_chunk(k0 + 32);  // prefetch overlaps mma below

#pragma unroll
        for (int ks = 0; ks < 4; ks++) {
            int kk = ks * 8;
            uint32_t a[2][4], bf[4][2];
#pragma unroll
            for (int mi = 0; mi < 2; mi++) {
                int row = warp_m * 32 + mi * 16 + gID;
                a[mi][0] = __float_as_uint(xs[row][kk + t4]);
                a[mi][1] = __float_as_uint(xs[row + 8][kk + t4]);
                a[mi][2] = __float_as_uint(xs[row][kk + t4 + 4]);
                a[mi][3] = __float_as_uint(xs[row + 8][kk + t4 + 4]);
            }
#pragma unroll
            for (int ni = 0; ni < 4; ni++) {
                int col = warp_n * 32 + ni * 8 + gID;
                bf[ni][0] = __float_as_uint(ws[kk + t4][col]);
                bf[ni][1] = __float_as_uint(ws[kk + t4 + 4][col]);
            }
#pragma unroll
            for (int mi = 0; mi < 2; mi++)
#pragma unroll
                for (int ni = 0; ni < 4; ni++)
                    mma_tf32(acc[mi][ni][0], acc[mi][ni][1], acc[mi][ni][2], acc[mi][ni][3],
                             a[mi][0], a[mi][1], a[mi][2], a[mi][3],
                             bf[ni][0], bf[ni][1]);
        }
        __syncthreads();
    }

    __nv_bfloat16* bdst = (m == 1) ? g_kb : g_vb;
#pragma unroll
    for (int mi = 0; mi < 2; mi++) {
        int r0 = node0 + warp_m * 32 + mi * 16 + gID;
#pragma unroll
        for (int ni = 0; ni < 4; ni++) {
            int cb = warp_n * 32 + ni * 8 + 2 * t4;
            float b0v = bias[cb], b1v = bias[cb + 1];
            float v00 = acc[mi][ni][0] + b0v, v01 = acc[mi][ni][1] + b1v;
            float v10 = acc[mi][ni][2] + b0v, v11 = acc[mi][ni][3] + b1v;
            if (m == 0) {
                if (r0 < NN)     { g_q[r0 * HC + cb] = v00; g_q[r0 * HC + cb + 1] = v01; }
                if (r0 + 8 < NN) { g_q[(r0 + 8) * HC + cb] = v10; g_q[(r0 + 8) * HC + cb + 1] = v11; }
            } else if (m == 3) {
                if (r0 < NN)     { g_s[r0 * HC + cb] = v00; g_s[r0 * HC + cb + 1] = v01; }
                if (r0 + 8 < NN) { g_s[(r0 + 8) * HC + cb] = v10; g_s[(r0 + 8) * HC + cb + 1] = v11; }
            } else {
                if (r0 < NN) {
                    __nv_bfloat162 p;
                    p.x = __float2bfloat16(v00); p.y = __float2bfloat16(v01);
                    *reinterpret_cast<__nv_bfloat162*>(&bdst[r0 * HC + cb]) = p;
                }
                if (r0 + 8 < NN) {
                    __nv_bfloat162 p;
                    p.x = __float2bfloat16(v10); p.y = __float2bfloat16(v11);
                    *reinterpret_cast<__nv_bfloat162*>(&bdst[(r0 + 8) * HC + cb]) = p;
                }
            }
        }
    }
}

// ---------------- per-node fused edge pass (gather, no atomics) ----------------
// One warp per destination node; 2-way edge unroll; bf16 k/v gathers
// (128B/edge-row vs 256B fp32 — bytes halved, traffic win preserved).
template <bool RELU, bool POOL>
__global__ __launch_bounds__(256) void node_edge_kernel(const float* __restrict__ We,
                                                        const int* __restrict__ batch) {
    __shared__ float Wes[EDIM * HC];
    for (int i = threadIdx.x; i < EDIM * HC; i += blockDim.x) Wes[i] = We[i];
    __syncthreads();

    int n = blockIdx.x * 8 + (threadIdx.x >> 5);
    int lane = threadIdx.x & 31;
    if (n >= NN) return;

    int r0 = g_rowptr[n];
    int r1 = g_rowptr[n + 1];

    float qv[NH], acc[NH], asum[NH];
#pragma unroll
    for (int j = 0; j < NH; j++) {
        qv[j] = g_q[n * HC + j * HID + lane];
        acc[j] = 0.f;
        asum[j] = 0.f;
    }

    int i = r0;
    for (; i + 1 < r1; i += 2) {
        int s0 = g_esrc[i], s1 = g_esrc[i + 1];
        float4 a0 = g_eea[i], a1 = g_eea[i + 1];
        float k0[NH], v0[NH], k1[NH], v1[NH];
#pragma unroll
        for (int j = 0; j < NH; j++) {
            int c = j * HID + lane;
            k0[j] = __bfloat162float(g_kb[s0 * HC + c]);
            v0[j] = __bfloat162float(g_vb[s0 * HC + c]);
            k1[j] = __bfloat162float(g_kb[s1 * HC + c]);
            v1[j] = __bfloat162float(g_vb[s1 * HC + c]);
        }
        float e0[NH], e1[NH], p0[NH], p1[NH];
#pragma unroll
        for (int j = 0; j < NH; j++) {
            int c = j * HID + lane;
            float w0 = Wes[c], w1 = Wes[HC + c], w2 = Wes[2 * HC + c], w3 = Wes[3 * HC + c];
            e0[j] = a0.x * w0 + a0.y * w1 + a0.z * w2 + a0.w * w3;
            e1[j] = a1.x * w0 + a1.y * w1 + a1.z * w2 + a1.w * w3;
            p0[j] = qv[j] * (k0[j] + e0[j]);
            p1[j] = qv[j] * (k1[j] + e1[j]);
        }
#pragma unroll
        for (int off = 16; off; off >>= 1) {
#pragma unroll
            for (int j = 0; j < NH; j++) {
                p0[j] += __shfl_xor_sync(0xffffffffu, p0[j], off);
                p1[j] += __shfl_xor_sync(0xffffffffu, p1[j], off);
            }
        }
#pragma unroll
        for (int j = 0; j < NH; j++) {
            float al0 = __expf(p0[j] * 0.17677669529663687f);
            float al1 = __expf(p1[j] * 0.17677669529663687f);
            asum[j] += al0 + al1;
            acc[j] = fmaf(v0[j] + e0[j], al0, acc[j]);
            acc[j] = fmaf(v1[j] + e1[j], al1, acc[j]);
        }
    }
    if (i < r1) {
        int s0 = g_esrc[i];
        float4 a0 = g_eea[i];
        float k0[NH], v0[NH], e0[NH], p0[NH];
#pragma unroll
        for (int j = 0; j < NH; j++) {
            int c = j * HID + lane;
            k0[j] = __bfloat162float(g_kb[s0 * HC + c]);
            v0[j] = __bfloat162float(g_vb[s0 * HC + c]);
        }
#pragma unroll
        for (int j = 0; j < NH; j++) {
            int c = j * HID + lane;
            e0[j] = a0.x * Wes[c] + a0.y * Wes[HC + c] + a0.z * Wes[2 * HC + c] + a0.w * Wes[3 * HC + c];
            p0[j] = qv[j] * (k0[j] + e0[j]);
        }
#pragma unroll
        for (int j = 0; j < NH; j++) {
#pragma unroll
            for (int off = 16; off; off >>= 1) p0[j] += __shfl_xor_sync(0xffffffffu, p0[j], off);
        }
#pragma unroll
        for (int j = 0; j < NH; j++) {
            float al = __expf(p0[j] * 0.17677669529663687f);
            asum[j] += al;
            acc[j] = fmaf(v0[j] + e0[j], al, acc[j]);
        }
    }

    int bslot = POOL ? batch[n] : 0;
#pragma unroll
    for (int j = 0; j < NH; j++) {
        int c = j * HID + lane;
        float h = acc[j] / (asum[j] + 1e-16f) + g_s[n * HC + c];
        if (RELU) h = fmaxf(h, 0.f);
        if (POOL) atomicAdd(&g_pooled[bslot * HC + c], h);
        else g_h[n * HC + c] = h;
    }
}

// ---------------- head ----------------
__global__ void head_kernel(const int* __restrict__ rt,
                            const float* __restrict__ hW,
                            const float* __restrict__ hb,
                            float* __restrict__ out) {
    int b = (blockIdx.x * blockDim.x + threadIdx.x) >> 5;
    int lane = threadIdx.x & 31;
    if (b >= BB) return;
    int r = rt[b];
    float acc = 0.f;
#pragma unroll
    for (int j = 0; j < NH; j++) {
        int c = j * HID + lane;
        acc = fmaf(g_pooled[b * HC + c], hW[r * HC + c], acc);
    }
#pragma unroll
    for (int off = 16; off; off >>= 1) acc += __shfl_xor_sync(0xffffffffu, acc, off);
    if (lane == 0) {
        float cnt = fmaxf(g_cnt[b], 1.f);
        out[b] = acc / cnt + hb[r];
    }
}

// ---------------- launch ----------------
extern "C" void kernel_launch(void* const* d_in, const int* in_sizes, int n_in,
                              void* d_out, int out_size) {
    const float* x     = (const float*)d_in[0];
    const int*   ei    = (const int*)d_in[1];
    const float* ea    = (const float*)d_in[2];
    const int*   batch = (const int*)d_in[3];
    const int*   rt    = (const int*)d_in[4];
    const float* Wq1 = (const float*)d_in[5];
    const float* bq1 = (const float*)d_in[6];
    const float* Wk1 = (const float*)d_in[7];
    const float* bk1 = (const float*)d_in[8];
    const float* Wv1 = (const float*)d_in[9];
    const float* bv1 = (const float*)d_in[10];
    const float* We1 = (const float*)d_in[11];
    const float* Ws1 = (const float*)d_in[12];
    const float* bs1 = (const float*)d_in[13];
    const float* Wq23 = (const float*)d_in[14];
    const float* bq23 = (const float*)d_in[15];
    const float* Wk23 = (const float*)d_in[16];
    const float* bk23 = (const float*)d_in[17];
    const float* Wv23 = (const float*)d_in[18];
    const float* bv23 = (const float*)d_in[19];
    const float* We23 = (const float*)d_in[20];
    const float* Ws23 = (const float*)d_in[21];
    const float* bs23 = (const float*)d_in[22];
    const float* headW = (const float*)d_in[23];
    const float* headb = (const float*)d_in[24];
    float* out = (float*)d_out;

    const dim3 gemm_grid((NN + 63) / 64, 4);
    const int node_blocks = (NN + 7) / 8;

    // ---- fork: first part of CSR build on side stream ----
    cudaEventRecord(g_evA, 0);
    cudaStreamWaitEvent(g_s2, g_evA, 0);
    zero_deg_kernel<<<256, 256, 0, g_s2>>>();       // kernel 1
    hist_kernel<<<1024, 256, 0, g_s2>>>(ei);        // kernel 2
    scanA_kernel<<<SCAN_B, SCAN_T, 0, g_s2>>>();    // kernel 3

    // ---- main stream: layer-1 GEMM enqueued 4th (profiled slot) ----
    gemm_tc_kernel<64, false><<<gemm_grid, 256>>>(x, Wq1, bq1, Wk1, bk1, Wv1, bv1, Ws1, bs1);

    // ---- rest of side-stream chain ----
    scanB_kernel<<<1, 256, 0, g_s2>>>();
    scanC_kernel<<<SCAN_B, SCAN_T, 0, g_s2>>>();
    bucket_kernel<<<1024, 256, 0, g_s2>>>(ei, ea);
    zero_pool_kernel<<<256, 256, 0, g_s2>>>();
    cnt_kernel<<<(NN + 255) / 256, 256, 0, g_s2>>>(batch);
    cudaEventRecord(g_evB, g_s2);

    cudaStreamWaitEvent(0, g_evB, 0);  // join before first edge pass
    node_edge_kernel<true, false><<<node_blocks, 256>>>(We1, batch);

    gemm_tc_kernel<128, true><<<gemm_grid, 256>>>(
        x, Wq23, bq23, Wk23, bk23, Wv23, bv23, Ws23, bs23);
    node_edge_kernel<true, false><<<node_blocks, 256>>>(We23, batch);

    gemm_tc_kernel<128, true><<<gemm_grid, 256>>>(
        x, Wq23 + HC * HC, bq23 + HC, Wk23 + HC * HC, bk23 + HC,
        Wv23 + HC * HC, bv23 + HC, Ws23 + HC * HC, bs23 + HC);
    node_edge_kernel<false, true><<<node_blocks, 256>>>(We23 + EDIM * HC, batch);

    head_kernel<<<(BB * 32 + 255) / 256, 256>>>(rt, headW, headb, out);
}

// round 14
// speedup vs baseline: 1.9736x; 1.2983x over previous
#include <cuda_runtime.h>
#include <cuda_bf16.h>
#include <cstdint>

#define NN 100000
#define EE 500000
#define BB 4096
#define HC 128
#define NH 4
#define HID 32
#define EDIM 4

#define SCAN_T 512
#define SCAN_B ((NN + SCAN_T - 1) / SCAN_T)  // 196

// ---------------- scratch (device globals: allocation-free) ----------------
__device__ float         g_q[NN * HC];
__device__ __align__(16) __nv_bfloat16 g_kb[NN * HC];   // k bf16
__device__ __align__(16) __nv_bfloat16 g_vb[NN * HC];   // v bf16
__device__ float         g_s[NN * HC];    // skip (x@Ws + bs)
__device__ float         g_h[NN * HC];    // layer output / next-layer input
__device__ float         g_pooled[BB * HC];
__device__ float         g_cnt[BB];
// CSR build
__device__ int    g_deg[NN];
__device__ int    g_incl[NN];
__device__ int    g_rowptr[NN + 1];
__device__ int    g_cursor[NN];
__device__ int    g_bsum[SCAN_B];
__device__ int    g_boff[SCAN_B];
__device__ int    g_esrc[EE];
__device__ float4 g_eea[EE];

// ---------------- side stream for overlap ----------------
static cudaStream_t g_s2;
static cudaEvent_t g_evA, g_evB;
namespace {
struct StreamInit {
    StreamInit() {
        cudaStreamCreateWithFlags(&g_s2, cudaStreamNonBlocking);
        cudaEventCreateWithFlags(&g_evA, cudaEventDisableTiming);
        cudaEventCreateWithFlags(&g_evB, cudaEventDisableTiming);
    }
} g_stream_init;
}

// ---------------- helpers ----------------
__device__ __forceinline__ float to_tf32(float x) {
    uint32_t u;
    asm("cvt.rna.tf32.f32 %0, %1;" : "=r"(u) : "f"(x));
    return __uint_as_float(u);
}

__device__ __forceinline__ void mma_tf32(float& c0, float& c1, float& c2, float& c3,
                                         uint32_t a0, uint32_t a1, uint32_t a2, uint32_t a3,
                                         uint32_t b0, uint32_t b1) {
    asm volatile(
        "mma.sync.aligned.m16n8k8.row.col.f32.tf32.tf32.f32 "
        "{%0,%1,%2,%3}, {%4,%5,%6,%7}, {%8,%9}, {%0,%1,%2,%3};"
        : "+f"(c0), "+f"(c1), "+f"(c2), "+f"(c3)
        : "r"(a0), "r"(a1), "r"(a2), "r"(a3), "r"(b0), "r"(b1));
}

// ---------------- CSR build ----------------
__global__ void zero_deg_kernel() {
    int stride = gridDim.x * blockDim.x;
    for (int i = blockIdx.x * blockDim.x + threadIdx.x; i < NN; i += stride) g_deg[i] = 0;
}

__global__ void hist_kernel(const int* __restrict__ ei) {
    int stride = gridDim.x * blockDim.x;
    for (int e = blockIdx.x * blockDim.x + threadIdx.x; e < EE; e += stride)
        atomicAdd(&g_deg[ei[EE + e]], 1);
}

__global__ void scanA_kernel() {
    __shared__ int s[SCAN_T];
    int tid = threadIdx.x;
    int i = blockIdx.x * SCAN_T + tid;
    int v = (i < NN) ? g_deg[i] : 0;
    s[tid] = v;
    __syncthreads();
#pragma unroll
    for (int off = 1; off < SCAN_T; off <<= 1) {
        int t = (tid >= off) ? s[tid - off] : 0;
        __syncthreads();
        s[tid] += t;
        __syncthreads();
    }
    if (i < NN) g_incl[i] = s[tid];
    if (tid == SCAN_T - 1) g_bsum[blockIdx.x] = s[tid];
}

__global__ void scanB_kernel() {
    __shared__ int s[256];
    int tid = threadIdx.x;
    int v = (tid < SCAN_B) ? g_bsum[tid] : 0;
    s[tid] = v;
    __syncthreads();
#pragma unroll
    for (int off = 1; off < 256; off <<= 1) {
        int t = (tid >= off) ? s[tid - off] : 0;
        __syncthreads();
        s[tid] += t;
        __syncthreads();
    }
    if (tid < SCAN_B) g_boff[tid] = s[tid] - v;
}

__global__ void scanC_kernel() {
    int i = blockIdx.x * SCAN_T + threadIdx.x;
    if (i < NN) {
        int excl = g_incl[i] - g_deg[i] + g_boff[blockIdx.x];
        g_rowptr[i] = excl;
        g_cursor[i] = excl;
    }
    if (i == 0) g_rowptr[NN] = EE;
}

__global__ void bucket_kernel(const int* __restrict__ ei, const float* __restrict__ ea) {
    int stride = gridDim.x * blockDim.x;
    for (int e = blockIdx.x * blockDim.x + threadIdx.x; e < EE; e += stride) {
        int dst = ei[EE + e];
        int pos = atomicAdd(&g_cursor[dst], 1);
        g_esrc[pos] = ei[e];
        g_eea[pos] = reinterpret_cast<const float4*>(ea)[e];
    }
}

// ---------------- zero pool + count ----------------
__global__ void zero_pool_kernel() {
    int stride = gridDim.x * blockDim.x;
    int i0 = blockIdx.x * blockDim.x + threadIdx.x;
    for (int i = i0; i < BB * HC; i += stride) g_pooled[i] = 0.f;
    for (int i = i0; i < BB; i += stride) g_cnt[i] = 0.f;
}

__global__ void cnt_kernel(const int* __restrict__ batch) {
    int n = blockIdx.x * blockDim.x + threadIdx.x;
    if (n < NN) atomicAdd(&g_cnt[batch[n]], 1.f);
}

// ---------------- split tensor-core GEMM (R13 winner, unchanged) ----------------
template <int D, bool USE_H>
__global__ __launch_bounds__(256, 2) void gemm_tc_kernel(
    const float* __restrict__ x,
    const float* __restrict__ Wq, const float* __restrict__ bq,
    const float* __restrict__ Wk, const float* __restrict__ bk,
    const float* __restrict__ Wv, const float* __restrict__ bv,
    const float* __restrict__ Ws, const float* __restrict__ bs) {
    __shared__ __align__(16) float xs[64][36];
    __shared__ __align__(16) float ws[32][136];

    const float* xin = USE_H ? g_h : x;
    const float* W;
    const float* bias;
    int m = blockIdx.y;
    if (m == 0)      { W = Wq; bias = bq; }
    else if (m == 1) { W = Wk; bias = bk; }
    else if (m == 2) { W = Wv; bias = bv; }
    else             { W = Ws; bias = bs; }

    int node0 = blockIdx.x * 64;
    int tid = threadIdx.x;
    int lane = tid & 31, wid = tid >> 5;
    int warp_m = wid >> 2, warp_n = wid & 3;  // 2 x 4, warp tile 32x32
    int gID = lane >> 2, t4 = lane & 3;

    const int xr_r[2] = {(tid + 0) >> 3, (tid + 256) >> 3};
    const int xr_c = (tid & 7) * 4;
    const int wr_r[4] = {(tid + 0) >> 5, (tid + 256) >> 5, (tid + 512) >> 5, (tid + 768) >> 5};
    const int wr_c = (tid & 31) * 4;

    float4 xr[2], wr[4];
    auto load_chunk = [&](int k0) {
#pragma unroll
        for (int t = 0; t < 2; t++) {
            int n = node0 + xr_r[t];
            xr[t] = (n < NN) ? *(const float4*)&xin[n * D + k0 + xr_c]
                             : make_float4(0.f, 0.f, 0.f, 0.f);
        }
#pragma unroll
        for (int t = 0; t < 4; t++)
            wr[t] = *(const float4*)&W[(k0 + wr_r[t]) * HC + wr_c];
    };
    auto store_chunk = [&]() {
#pragma unroll
        for (int t = 0; t < 2; t++) {
            float* xp = &xs[xr_r[t]][xr_c];
            xp[0] = to_tf32(xr[t].x); xp[1] = to_tf32(xr[t].y);
            xp[2] = to_tf32(xr[t].z); xp[3] = to_tf32(xr[t].w);
        }
#pragma unroll
        for (int t = 0; t < 4; t++) {
            float* wp = &ws[wr_r[t]][wr_c];
            wp[0] = to_tf32(wr[t].x); wp[1] = to_tf32(wr[t].y);
            wp[2] = to_tf32(wr[t].z); wp[3] = to_tf32(wr[t].w);
        }
    };

    float acc[2][4][4];
#pragma unroll
    for (int mi = 0; mi < 2; mi++)
#pragma unroll
        for (int ni = 0; ni < 4; ni++)
#pragma unroll
            for (int r = 0; r < 4; r++) acc[mi][ni][r] = 0.f;

    load_chunk(0);
#pragma unroll
    for (int k0 = 0; k0 < D; k0 += 32) {
        store_chunk();
        __syncthreads();
        if (k0 + 32 < D) load_chunk(k0 + 32);  // prefetch overlaps mma below

#pragma unroll
        for (int ks = 0; ks < 4; ks++) {
            int kk = ks * 8;
            uint32_t a[2][4], bf[4][2];
#pragma unroll
            for (int mi = 0; mi < 2; mi++) {
                int row = warp_m * 32 + mi * 16 + gID;
                a[mi][0] = __float_as_uint(xs[row][kk + t4]);
                a[mi][1] = __float_as_uint(xs[row + 8][kk + t4]);
                a[mi][2] = __float_as_uint(xs[row][kk + t4 + 4]);
                a[mi][3] = __float_as_uint(xs[row + 8][kk + t4 + 4]);
            }
#pragma unroll
            for (int ni = 0; ni < 4; ni++) {
                int col = warp_n * 32 + ni * 8 + gID;
                bf[ni][0] = __float_as_uint(ws[kk + t4][col]);
                bf[ni][1] = __float_as_uint(ws[kk + t4 + 4][col]);
            }
#pragma unroll
            for (int mi = 0; mi < 2; mi++)
#pragma unroll
                for (int ni = 0; ni < 4; ni++)
                    mma_tf32(acc[mi][ni][0], acc[mi][ni][1], acc[mi][ni][2], acc[mi][ni][3],
                             a[mi][0], a[mi][1], a[mi][2], a[mi][3],
                             bf[ni][0], bf[ni][1]);
        }
        __syncthreads();
    }

    __nv_bfloat16* bdst = (m == 1) ? g_kb : g_vb;
#pragma unroll
    for (int mi = 0; mi < 2; mi++) {
        int r0 = node0 + warp_m * 32 + mi * 16 + gID;
#pragma unroll
        for (int ni = 0; ni < 4; ni++) {
            int cb = warp_n * 32 + ni * 8 + 2 * t4;
            float b0v = bias[cb], b1v = bias[cb + 1];
            float v00 = acc[mi][ni][0] + b0v, v01 = acc[mi][ni][1] + b1v;
            float v10 = acc[mi][ni][2] + b0v, v11 = acc[mi][ni][3] + b1v;
            if (m == 0) {
                if (r0 < NN)     { g_q[r0 * HC + cb] = v00; g_q[r0 * HC + cb + 1] = v01; }
                if (r0 + 8 < NN) { g_q[(r0 + 8) * HC + cb] = v10; g_q[(r0 + 8) * HC + cb + 1] = v11; }
            } else if (m == 3) {
                if (r0 < NN)     { g_s[r0 * HC + cb] = v00; g_s[r0 * HC + cb + 1] = v01; }
                if (r0 + 8 < NN) { g_s[(r0 + 8) * HC + cb] = v10; g_s[(r0 + 8) * HC + cb + 1] = v11; }
            } else {
                if (r0 < NN) {
                    __nv_bfloat162 p;
                    p.x = __float2bfloat16(v00); p.y = __float2bfloat16(v01);
                    *reinterpret_cast<__nv_bfloat162*>(&bdst[r0 * HC + cb]) = p;
                }
                if (r0 + 8 < NN) {
                    __nv_bfloat162 p;
                    p.x = __float2bfloat16(v10); p.y = __float2bfloat16(v11);
                    *reinterpret_cast<__nv_bfloat162*>(&bdst[(r0 + 8) * HC + cb]) = p;
                }
            }
        }
    }
}

// ---------------- per-node fused edge pass (lane = head x column-quad) ----------------
// Lane = head*8 + sub; each lane owns 4 consecutive columns of its head.
// Per edge: one 8B uint2 gather each for k and v, 3-shfl reduce over 8 lanes
// serving all 4 heads at once, 1 expf per lane. q/s/h are float4 vectorized.
template <bool RELU, bool POOL>
__global__ __launch_bounds__(256) void node_edge_kernel(const float* __restrict__ We,
                                                        const int* __restrict__ batch) {
    __shared__ float Wes[EDIM * HC];
    for (int i = threadIdx.x; i < EDIM * HC; i += blockDim.x) Wes[i] = We[i];
    __syncthreads();

    int n = blockIdx.x * 8 + (threadIdx.x >> 5);
    int lane = threadIdx.x & 31;
    if (n >= NN) return;

    int c0 = lane * 4;  // head = lane>>3 owns cols [32h,32h+32); sub = lane&7 -> 4 consecutive cols

    // per-lane We slice (fixed columns): Wreg[d][u]
    float Wreg[EDIM][4];
#pragma unroll
    for (int d = 0; d < EDIM; d++) {
        float4 w = *reinterpret_cast<const float4*>(&Wes[d * HC + c0]);
        Wreg[d][0] = w.x; Wreg[d][1] = w.y; Wreg[d][2] = w.z; Wreg[d][3] = w.w;
    }

    float4 q4 = *reinterpret_cast<const float4*>(&g_q[n * HC + c0]);
    float qv[4] = {q4.x, q4.y, q4.z, q4.w};
    float acc[4] = {0.f, 0.f, 0.f, 0.f};
    float asum = 0.f;

    int r0 = g_rowptr[n];
    int r1 = g_rowptr[n + 1];

    auto unpack = [](uint2 r, float* out) {
        float2 lo = __bfloat1622float2(*reinterpret_cast<__nv_bfloat162*>(&r.x));
        float2 hi = __bfloat1622float2(*reinterpret_cast<__nv_bfloat162*>(&r.y));
        out[0] = lo.x; out[1] = lo.y; out[2] = hi.x; out[3] = hi.y;
    };

    int i = r0;
    for (; i + 1 < r1; i += 2) {
        int s0 = g_esrc[i], s1 = g_esrc[i + 1];
        float4 a0 = g_eea[i], a1 = g_eea[i + 1];
        uint2 kr0 = *reinterpret_cast<const uint2*>(&g_kb[s0 * HC + c0]);
        uint2 vr0 = *reinterpret_cast<const uint2*>(&g_vb[s0 * HC + c0]);
        uint2 kr1 = *reinterpret_cast<const uint2*>(&g_kb[s1 * HC + c0]);
        uint2 vr1 = *reinterpret_cast<const uint2*>(&g_vb[s1 * HC + c0]);
        float k0[4], v0[4], k1[4], v1[4];
        unpack(kr0, k0); unpack(vr0, v0);
        unpack(kr1, k1); unpack(vr1, v1);

        float e0[4], e1[4];
        float p0 = 0.f, p1 = 0.f;
#pragma unroll
        for (int u = 0; u < 4; u++) {
            e0[u] = a0.x * Wreg[0][u] + a0.y * Wreg[1][u] + a0.z * Wreg[2][u] + a0.w * Wreg[3][u];
            e1[u] = a1.x * Wreg[0][u] + a1.y * Wreg[1][u] + a1.z * Wreg[2][u] + a1.w * Wreg[3][u];
            p0 = fmaf(qv[u], k0[u] + e0[u], p0);
            p1 = fmaf(qv[u], k1[u] + e1[u], p1);
        }
        // 3-shfl butterfly within the 8-lane head group (serves all heads at once)
#pragma unroll
        for (int off = 4; off; off >>= 1) {
            p0 += __shfl_xor_sync(0xffffffffu, p0, off);
            p1 += __shfl_xor_sync(0xffffffffu, p1, off);
        }
        float al0 = __expf(p0 * 0.17677669529663687f);  // 1/sqrt(32)
        float al1 = __expf(p1 * 0.17677669529663687f);
        asum += al0 + al1;
#pragma unroll
        for (int u = 0; u < 4; u++) {
            acc[u] = fmaf(v0[u] + e0[u], al0, acc[u]);
            acc[u] = fmaf(v1[u] + e1[u], al1, acc[u]);
        }
    }
    if (i < r1) {
        int s0 = g_esrc[i];
        float4 a0 = g_eea[i];
        uint2 kr0 = *reinterpret_cast<const uint2*>(&g_kb[s0 * HC + c0]);
        uint2 vr0 = *reinterpret_cast<const uint2*>(&g_vb[s0 * HC + c0]);
        float k0[4], v0[4];
        unpack(kr0, k0); unpack(vr0, v0);
        float e0[4];
        float p0 = 0.f;
#pragma unroll
        for (int u = 0; u < 4; u++) {
            e0[u] = a0.x * Wreg[0][u] + a0.y * Wreg[1][u] + a0.z * Wreg[2][u] + a0.w * Wreg[3][u];
            p0 = fmaf(qv[u], k0[u] + e0[u], p0);
        }
#pragma unroll
        for (int off = 4; off; off >>= 1) p0 += __shfl_xor_sync(0xffffffffu, p0, off);
        float al0 = __expf(p0 * 0.17677669529663687f);
        asum += al0;
#pragma unroll
        for (int u = 0; u < 4; u++) acc[u] = fmaf(v0[u] + e0[u], al0, acc[u]);
    }

    float inv = 1.f / (asum + 1e-16f);
    float4 s4 = *reinterpret_cast<const float4*>(&g_s[n * HC + c0]);
    float h0 = acc[0] * inv + s4.x;
    float h1 = acc[1] * inv + s4.y;
    float h2 = acc[2] * inv + s4.z;
    float h3 = acc[3] * inv + s4.w;
    if (RELU) {
        h0 = fmaxf(h0, 0.f); h1 = fmaxf(h1, 0.f);
        h2 = fmaxf(h2, 0.f); h3 = fmaxf(h3, 0.f);
    }
    if (POOL) {
        int b = batch[n];
        atomicAdd(&g_pooled[b * HC + c0 + 0], h0);
        atomicAdd(&g_pooled[b * HC + c0 + 1], h1);
        atomicAdd(&g_pooled[b * HC + c0 + 2], h2);
        atomicAdd(&g_pooled[b * HC + c0 + 3], h3);
    } else {
        *reinterpret_cast<float4*>(&g_h[n * HC + c0]) = make_float4(h0, h1, h2, h3);
    }
}

// ---------------- head ----------------
__global__ void head_kernel(const int* __restrict__ rt,
                            const float* __restrict__ hW,
                            const float* __restrict__ hb,
                            float* __restrict__ out) {
    int b = (blockIdx.x * blockDim.x + threadIdx.x) >> 5;
    int lane = threadIdx.x & 31;
    if (b >= BB) return;
    int r = rt[b];
    float acc = 0.f;
#pragma unroll
    for (int j = 0; j < NH; j++) {
        int c = j * HID + lane;
        acc = fmaf(g_pooled[b * HC + c], hW[r * HC + c], acc);
    }
#pragma unroll
    for (int off = 16; off; off >>= 1) acc += __shfl_xor_sync(0xffffffffu, acc, off);
    if (lane == 0) {
        float cnt = fmaxf(g_cnt[b], 1.f);
        out[b] = acc / cnt + hb[r];
    }
}

// ---------------- launch ----------------
extern "C" void kernel_launch(void* const* d_in, const int* in_sizes, int n_in,
                              void* d_out, int out_size) {
    const float* x     = (const float*)d_in[0];
    const int*   ei    = (const int*)d_in[1];
    const float* ea    = (const float*)d_in[2];
    const int*   batch = (const int*)d_in[3];
    const int*   rt    = (const int*)d_in[4];
    const float* Wq1 = (const float*)d_in[5];
    const float* bq1 = (const float*)d_in[6];
    const float* Wk1 = (const float*)d_in[7];
    const float* bk1 = (const float*)d_in[8];
    const float* Wv1 = (const float*)d_in[9];
    const float* bv1 = (const float*)d_in[10];
    const float* We1 = (const float*)d_in[11];
    const float* Ws1 = (const float*)d_in[12];
    const float* bs1 = (const float*)d_in[13];
    const float* Wq23 = (const float*)d_in[14];
    const float* bq23 = (const float*)d_in[15];
    const float* Wk23 = (const float*)d_in[16];
    const float* bk23 = (const float*)d_in[17];
    const float* Wv23 = (const float*)d_in[18];
    const float* bv23 = (const float*)d_in[19];
    const float* We23 = (const float*)d_in[20];
    const float* Ws23 = (const float*)d_in[21];
    const float* bs23 = (const float*)d_in[22];
    const float* headW = (const float*)d_in[23];
    const float* headb = (const float*)d_in[24];
    float* out = (float*)d_out;

    const dim3 gemm_grid((NN + 63) / 64, 4);
    const int node_blocks = (NN + 7) / 8;

    // ---- fork: first part of CSR build on side stream ----
    cudaEventRecord(g_evA, 0);
    cudaStreamWaitEvent(g_s2, g_evA, 0);
    zero_deg_kernel<<<256, 256, 0, g_s2>>>();       // kernel 1
    hist_kernel<<<1024, 256, 0, g_s2>>>(ei);        // kernel 2
    scanA_kernel<<<SCAN_B, SCAN_T, 0, g_s2>>>();    // kernel 3

    // ---- main stream: layer-1 GEMM enqueued 4th (profiled slot) ----
    gemm_tc_kernel<64, false><<<gemm_grid, 256>>>(x, Wq1, bq1, Wk1, bk1, Wv1, bv1, Ws1, bs1);

    // ---- rest of side-stream chain ----
    scanB_kernel<<<1, 256, 0, g_s2>>>();
    scanC_kernel<<<SCAN_B, SCAN_T, 0, g_s2>>>();
    bucket_kernel<<<1024, 256, 0, g_s2>>>(ei, ea);
    zero_pool_kernel<<<256, 256, 0, g_s2>>>();
    cnt_kernel<<<(NN + 255) / 256, 256, 0, g_s2>>>(batch);
    cudaEventRecord(g_evB, g_s2);

    cudaStreamWaitEvent(0, g_evB, 0);  // join before first edge pass
    node_edge_kernel<true, false><<<node_blocks, 256>>>(We1, batch);

    gemm_tc_kernel<128, true><<<gemm_grid, 256>>>(
        x, Wq23, bq23, Wk23, bk23, Wv23, bv23, Ws23, bs23);
    node_edge_kernel<true, false><<<node_blocks, 256>>>(We23, batch);

    gemm_tc_kernel<128, true><<<gemm_grid, 256>>>(
        x, Wq23 + HC * HC, bq23 + HC, Wk23 + HC * HC, bk23 + HC,
        Wv23 + HC * HC, bv23 + HC, Ws23 + HC * HC, bs23 + HC);
    node_edge_kernel<false, true><<<node_blocks, 256>>>(We23 + EDIM * HC, batch);

    head_kernel<<<(BB * 32 + 255) / 256, 256>>>(rt, headW, headb, out);
}

// round 15
// speedup vs baseline: 2.0880x; 1.0580x over previous
#include <cuda_runtime.h>
#include <cuda_bf16.h>
#include <cstdint>

#define NN 100000
#define EE 500000
#define BB 4096
#define HC 128
#define NH 4
#define HID 32
#define EDIM 4

#define SCAN_T 512
#define SCAN_B ((NN + SCAN_T - 1) / SCAN_T)  // 196

#define NTILES ((NN + 63) / 64)  // 1563
#define GEMM_GX 74               // 74*4 = 296 blocks = 2/SM, one wave

// ---------------- scratch (device globals: allocation-free) ----------------
__device__ float         g_q[NN * HC];
__device__ __align__(16) __nv_bfloat16 g_kb[NN * HC];   // k bf16
__device__ __align__(16) __nv_bfloat16 g_vb[NN * HC];   // v bf16
__device__ float         g_s[NN * HC];    // skip (x@Ws + bs)
__device__ float         g_h[NN * HC];    // layer output / next-layer input
__device__ float         g_pooled[BB * HC];
__device__ float         g_cnt[BB];
// CSR build
__device__ int    g_deg[NN];
__device__ int    g_incl[NN];
__device__ int    g_rowptr[NN + 1];
__device__ int    g_cursor[NN];
__device__ int    g_bsum[SCAN_B];
__device__ int    g_boff[SCAN_B];
__device__ int    g_esrc[EE];
__device__ float4 g_eea[EE];

// ---------------- side stream for overlap ----------------
static cudaStream_t g_s2;
static cudaEvent_t g_evA, g_evB;
namespace {
struct StreamInit {
    StreamInit() {
        cudaStreamCreateWithFlags(&g_s2, cudaStreamNonBlocking);
        cudaEventCreateWithFlags(&g_evA, cudaEventDisableTiming);
        cudaEventCreateWithFlags(&g_evB, cudaEventDisableTiming);
    }
} g_stream_init;
}

// ---------------- helpers ----------------
__device__ __forceinline__ float to_tf32(float x) {
    uint32_t u;
    asm("cvt.rna.tf32.f32 %0, %1;" : "=r"(u) : "f"(x));
    return __uint_as_float(u);
}

__device__ __forceinline__ void mma_tf32(float& c0, float& c1, float& c2, float& c3,
                                         uint32_t a0, uint32_t a1, uint32_t a2, uint32_t a3,
                                         uint32_t b0, uint32_t b1) {
    asm volatile(
        "mma.sync.aligned.m16n8k8.row.col.f32.tf32.tf32.f32 "
        "{%0,%1,%2,%3}, {%4,%5,%6,%7}, {%8,%9}, {%0,%1,%2,%3};"
        : "+f"(c0), "+f"(c1), "+f"(c2), "+f"(c3)
        : "r"(a0), "r"(a1), "r"(a2), "r"(a3), "r"(b0), "r"(b1));
}

// ---------------- CSR build ----------------
__global__ void zero_deg_kernel() {
    int stride = gridDim.x * blockDim.x;
    for (int i = blockIdx.x * blockDim.x + threadIdx.x; i < NN; i += stride) g_deg[i] = 0;
}

__global__ void hist_kernel(const int* __restrict__ ei) {
    int stride = gridDim.x * blockDim.x;
    for (int e = blockIdx.x * blockDim.x + threadIdx.x; e < EE; e += stride)
        atomicAdd(&g_deg[ei[EE + e]], 1);
}

__global__ void scanA_kernel() {
    __shared__ int s[SCAN_T];
    int tid = threadIdx.x;
    int i = blockIdx.x * SCAN_T + tid;
    int v = (i < NN) ? g_deg[i] : 0;
    s[tid] = v;
    __syncthreads();
#pragma unroll
    for (int off = 1; off < SCAN_T; off <<= 1) {
        int t = (tid >= off) ? s[tid - off] : 0;
        __syncthreads();
        s[tid] += t;
        __syncthreads();
    }
    if (i < NN) g_incl[i] = s[tid];
    if (tid == SCAN_T - 1) g_bsum[blockIdx.x] = s[tid];
}

__global__ void scanB_kernel() {
    __shared__ int s[256];
    int tid = threadIdx.x;
    int v = (tid < SCAN_B) ? g_bsum[tid] : 0;
    s[tid] = v;
    __syncthreads();
#pragma unroll
    for (int off = 1; off < 256; off <<= 1) {
        int t = (tid >= off) ? s[tid - off] : 0;
        __syncthreads();
        s[tid] += t;
        __syncthreads();
    }
    if (tid < SCAN_B) g_boff[tid] = s[tid] - v;
}

__global__ void scanC_kernel() {
    int i = blockIdx.x * SCAN_T + threadIdx.x;
    if (i < NN) {
        int excl = g_incl[i] - g_deg[i] + g_boff[blockIdx.x];
        g_rowptr[i] = excl;
        g_cursor[i] = excl;
    }
    if (i == 0) g_rowptr[NN] = EE;
}

__global__ void bucket_kernel(const int* __restrict__ ei, const float* __restrict__ ea) {
    int stride = gridDim.x * blockDim.x;
    for (int e = blockIdx.x * blockDim.x + threadIdx.x; e < EE; e += stride) {
        int dst = ei[EE + e];
        int pos = atomicAdd(&g_cursor[dst], 1);
        g_esrc[pos] = ei[e];
        g_eea[pos] = reinterpret_cast<const float4*>(ea)[e];
    }
}

// ---------------- zero pool + count ----------------
__global__ void zero_pool_kernel() {
    int stride = gridDim.x * blockDim.x;
    int i0 = blockIdx.x * blockDim.x + threadIdx.x;
    for (int i = i0; i < BB * HC; i += stride) g_pooled[i] = 0.f;
    for (int i = i0; i < BB; i += stride) g_cnt[i] = 0.f;
}

__global__ void cnt_kernel(const int* __restrict__ batch) {
    int n = blockIdx.x * blockDim.x + threadIdx.x;
    if (n < NN) atomicAdd(&g_cnt[batch[n]], 1.f);
}

// ---------------- persistent W-resident tensor-core GEMM ----------------
// One matrix per block (blockIdx.y). The FULL DxHC weight matrix is loaded into
// dynamic smem once (tf32, stride 136 = conflict-free b-frags), then the block
// loops over x-tiles with register prefetch. Removes all per-tile W LDG/STS
// (the dominant redundant L1 traffic) and 6 of 8 per-tile syncs.
template <int D, bool USE_H>
__global__ __launch_bounds__(256, 2) void gemm_tc_kernel(
    const float* __restrict__ x,
    const float* __restrict__ Wq, const float* __restrict__ bq,
    const float* __restrict__ Wk, const float* __restrict__ bk,
    const float* __restrict__ Wv, const float* __restrict__ bv,
    const float* __restrict__ Ws, const float* __restrict__ bs) {
    constexpr int XST = D + 4;      // bank stride 4 mod 32 -> conflict-free a-frags
    constexpr int NXI = D / 16;     // x-tile float4 loads per thread
    extern __shared__ __align__(16) float smem_dyn[];
    float* ws = smem_dyn;           // [D][136]
    float* xs = smem_dyn + D * 136; // [64][XST]

    const float* xin = USE_H ? g_h : x;
    const float* W;
    const float* bias;
    int m = blockIdx.y;
    if (m == 0)      { W = Wq; bias = bq; }
    else if (m == 1) { W = Wk; bias = bk; }
    else if (m == 2) { W = Wv; bias = bv; }
    else             { W = Ws; bias = bs; }

    int tid = threadIdx.x;
    int lane = tid & 31, wid = tid >> 5;
    int warp_m = wid >> 2, warp_n = wid & 3;  // 2 x 4, warp tile 32x32
    int gID = lane >> 2, t4 = lane & 3;

    // ---- load full W into smem (tf32) ----
    for (int idx = tid; idx < D * 32; idx += 256) {
        int r = idx >> 5, cg = (idx & 31) * 4;
        float4 w = *(const float4*)&W[r * HC + cg];
        float* wp = &ws[r * 136 + cg];
        wp[0] = to_tf32(w.x); wp[1] = to_tf32(w.y);
        wp[2] = to_tf32(w.z); wp[3] = to_tf32(w.w);
    }

    // ---- hoist bias to registers ----
    float bia[4][2];
#pragma unroll
    for (int ni = 0; ni < 4; ni++) {
        int cb = warp_n * 32 + ni * 8 + 2 * t4;
        bia[ni][0] = bias[cb];
        bia[ni][1] = bias[cb + 1];
    }
    __syncthreads();

    __nv_bfloat16* bdst = (m == 1) ? g_kb : g_vb;

    float4 xr[NXI];
    auto load_x = [&](int tl) {
#pragma unroll
        for (int t = 0; t < NXI; t++) {
            int idx = tid + t * 256;
            int row = idx / (D / 4);
            int cg = (idx % (D / 4)) * 4;
            int n = tl * 64 + row;
            xr[t] = (n < NN) ? *(const float4*)&xin[n * D + cg]
                             : make_float4(0.f, 0.f, 0.f, 0.f);
        }
    };

    int tile = blockIdx.x;
    if (tile < NTILES) load_x(tile);
    for (; tile < NTILES; tile += GEMM_GX) {
        // store prefetched x tile (tf32)
#pragma unroll
        for (int t = 0; t < NXI; t++) {
            int idx = tid + t * 256;
            int row = idx / (D / 4);
            int cg = (idx % (D / 4)) * 4;
            float* xp = &xs[row * XST + cg];
            xp[0] = to_tf32(xr[t].x); xp[1] = to_tf32(xr[t].y);
            xp[2] = to_tf32(xr[t].z); xp[3] = to_tf32(xr[t].w);
        }
        __syncthreads();
        int nxt = tile + GEMM_GX;
        if (nxt < NTILES) load_x(nxt);  // LDG in flight during the mma chain

        float acc[2][4][4];
#pragma unroll
        for (int mi = 0; mi < 2; mi++)
#pragma unroll
            for (int ni = 0; ni < 4; ni++)
#pragma unroll
                for (int r = 0; r < 4; r++) acc[mi][ni][r] = 0.f;

#pragma unroll
        for (int ks = 0; ks < D / 8; ks++) {
            int kk = ks * 8;
            uint32_t a[2][4], bf[4][2];
#pragma unroll
            for (int mi = 0; mi < 2; mi++) {
                int row = warp_m * 32 + mi * 16 + gID;
                a[mi][0] = __float_as_uint(xs[row * XST + kk + t4]);
                a[mi][1] = __float_as_uint(xs[(row + 8) * XST + kk + t4]);
                a[mi][2] = __float_as_uint(xs[row * XST + kk + t4 + 4]);
                a[mi][3] = __float_as_uint(xs[(row + 8) * XST + kk + t4 + 4]);
            }
#pragma unroll
            for (int ni = 0; ni < 4; ni++) {
                int col = warp_n * 32 + ni * 8 + gID;
                bf[ni][0] = __float_as_uint(ws[(kk + t4) * 136 + col]);
                bf[ni][1] = __float_as_uint(ws[(kk + t4 + 4) * 136 + col]);
            }
#pragma unroll
            for (int mi = 0; mi < 2; mi++)
#pragma unroll
                for (int ni = 0; ni < 4; ni++)
                    mma_tf32(acc[mi][ni][0], acc[mi][ni][1], acc[mi][ni][2], acc[mi][ni][3],
                             a[mi][0], a[mi][1], a[mi][2], a[mi][3],
                             bf[ni][0], bf[ni][1]);
        }
        __syncthreads();  // protect xs before next tile's store

        // epilogue for this tile
        int node0 = tile * 64;
#pragma unroll
        for (int mi = 0; mi < 2; mi++) {
            int r0 = node0 + warp_m * 32 + mi * 16 + gID;
#pragma unroll
            for (int ni = 0; ni < 4; ni++) {
                int cb = warp_n * 32 + ni * 8 + 2 * t4;
                float v00 = acc[mi][ni][0] + bia[ni][0], v01 = acc[mi][ni][1] + bia[ni][1];
                float v10 = acc[mi][ni][2] + bia[ni][0], v11 = acc[mi][ni][3] + bia[ni][1];
                if (m == 0) {
                    if (r0 < NN)     { g_q[r0 * HC + cb] = v00; g_q[r0 * HC + cb + 1] = v01; }
                    if (r0 + 8 < NN) { g_q[(r0 + 8) * HC + cb] = v10; g_q[(r0 + 8) * HC + cb + 1] = v11; }
                } else if (m == 3) {
                    if (r0 < NN)     { g_s[r0 * HC + cb] = v00; g_s[r0 * HC + cb + 1] = v01; }
                    if (r0 + 8 < NN) { g_s[(r0 + 8) * HC + cb] = v10; g_s[(r0 + 8) * HC + cb + 1] = v11; }
                } else {
                    if (r0 < NN) {
                        __nv_bfloat162 p;
                        p.x = __float2bfloat16(v00); p.y = __float2bfloat16(v01);
                        *reinterpret_cast<__nv_bfloat162*>(&bdst[r0 * HC + cb]) = p;
                    }
                    if (r0 + 8 < NN) {
                        __nv_bfloat162 p;
                        p.x = __float2bfloat16(v10); p.y = __float2bfloat16(v11);
                        *reinterpret_cast<__nv_bfloat162*>(&bdst[(r0 + 8) * HC + cb]) = p;
                    }
                }
            }
        }
    }
}

// ---------------- per-node fused edge pass (R14 winner, unchanged) ----------------
template <bool RELU, bool POOL>
__global__ __launch_bounds__(256) void node_edge_kernel(const float* __restrict__ We,
                                                        const int* __restrict__ batch) {
    __shared__ float Wes[EDIM * HC];
    for (int i = threadIdx.x; i < EDIM * HC; i += blockDim.x) Wes[i] = We[i];
    __syncthreads();

    int n = blockIdx.x * 8 + (threadIdx.x >> 5);
    int lane = threadIdx.x & 31;
    if (n >= NN) return;

    int c0 = lane * 4;

    float Wreg[EDIM][4];
#pragma unroll
    for (int d = 0; d < EDIM; d++) {
        float4 w = *reinterpret_cast<const float4*>(&Wes[d * HC + c0]);
        Wreg[d][0] = w.x; Wreg[d][1] = w.y; Wreg[d][2] = w.z; Wreg[d][3] = w.w;
    }

    float4 q4 = *reinterpret_cast<const float4*>(&g_q[n * HC + c0]);
    float qv[4] = {q4.x, q4.y, q4.z, q4.w};
    float acc[4] = {0.f, 0.f, 0.f, 0.f};
    float asum = 0.f;

    int r0 = g_rowptr[n];
    int r1 = g_rowptr[n + 1];

    auto unpack = [](uint2 r, float* out) {
        float2 lo = __bfloat1622float2(*reinterpret_cast<__nv_bfloat162*>(&r.x));
        float2 hi = __bfloat1622float2(*reinterpret_cast<__nv_bfloat162*>(&r.y));
        out[0] = lo.x; out[1] = lo.y; out[2] = hi.x; out[3] = hi.y;
    };

    int i = r0;
    for (; i + 1 < r1; i += 2) {
        int s0 = g_esrc[i], s1 = g_esrc[i + 1];
        float4 a0 = g_eea[i], a1 = g_eea[i + 1];
        uint2 kr0 = *reinterpret_cast<const uint2*>(&g_kb[s0 * HC + c0]);
        uint2 vr0 = *reinterpret_cast<const uint2*>(&g_vb[s0 * HC + c0]);
        uint2 kr1 = *reinterpret_cast<const uint2*>(&g_kb[s1 * HC + c0]);
        uint2 vr1 = *reinterpret_cast<const uint2*>(&g_vb[s1 * HC + c0]);
        float k0[4], v0[4], k1[4], v1[4];
        unpack(kr0, k0); unpack(vr0, v0);
        unpack(kr1, k1); unpack(vr1, v1);

        float e0[4], e1[4];
        float p0 = 0.f, p1 = 0.f;
#pragma unroll
        for (int u = 0; u < 4; u++) {
            e0[u] = a0.x * Wreg[0][u] + a0.y * Wreg[1][u] + a0.z * Wreg[2][u] + a0.w * Wreg[3][u];
            e1[u] = a1.x * Wreg[0][u] + a1.y * Wreg[1][u] + a1.z * Wreg[2][u] + a1.w * Wreg[3][u];
            p0 = fmaf(qv[u], k0[u] + e0[u], p0);
            p1 = fmaf(qv[u], k1[u] + e1[u], p1);
        }
#pragma unroll
        for (int off = 4; off; off >>= 1) {
            p0 += __shfl_xor_sync(0xffffffffu, p0, off);
            p1 += __shfl_xor_sync(0xffffffffu, p1, off);
        }
        float al0 = __expf(p0 * 0.17677669529663687f);
        float al1 = __expf(p1 * 0.17677669529663687f);
        asum += al0 + al1;
#pragma unroll
        for (int u = 0; u < 4; u++) {
            acc[u] = fmaf(v0[u] + e0[u], al0, acc[u]);
            acc[u] = fmaf(v1[u] + e1[u], al1, acc[u]);
        }
    }
    if (i < r1) {
        int s0 = g_esrc[i];
        float4 a0 = g_eea[i];
        uint2 kr0 = *reinterpret_cast<const uint2*>(&g_kb[s0 * HC + c0]);
        uint2 vr0 = *reinterpret_cast<const uint2*>(&g_vb[s0 * HC + c0]);
        float k0[4], v0[4];
        unpack(kr0, k0); unpack(vr0, v0);
        float e0[4];
        float p0 = 0.f;
#pragma unroll
        for (int u = 0; u < 4; u++) {
            e0[u] = a0.x * Wreg[0][u] + a0.y * Wreg[1][u] + a0.z * Wreg[2][u] + a0.w * Wreg[3][u];
            p0 = fmaf(qv[u], k0[u] + e0[u], p0);
        }
#pragma unroll
        for (int off = 4; off; off >>= 1) p0 += __shfl_xor_sync(0xffffffffu, p0, off);
        float al0 = __expf(p0 * 0.17677669529663687f);
        asum += al0;
#pragma unroll
        for (int u = 0; u < 4; u++) acc[u] = fmaf(v0[u] + e0[u], al0, acc[u]);
    }

    float inv = 1.f / (asum + 1e-16f);
    float4 s4 = *reinterpret_cast<const float4*>(&g_s[n * HC + c0]);
    float h0 = acc[0] * inv + s4.x;
    float h1 = acc[1] * inv + s4.y;
    float h2 = acc[2] * inv + s4.z;
    float h3 = acc[3] * inv + s4.w;
    if (RELU) {
        h0 = fmaxf(h0, 0.f); h1 = fmaxf(h1, 0.f);
        h2 = fmaxf(h2, 0.f); h3 = fmaxf(h3, 0.f);
    }
    if (POOL) {
        int b = batch[n];
        atomicAdd(&g_pooled[b * HC + c0 + 0], h0);
        atomicAdd(&g_pooled[b * HC + c0 + 1], h1);
        atomicAdd(&g_pooled[b * HC + c0 + 2], h2);
        atomicAdd(&g_pooled[b * HC + c0 + 3], h3);
    } else {
        *reinterpret_cast<float4*>(&g_h[n * HC + c0]) = make_float4(h0, h1, h2, h3);
    }
}

// ---------------- head ----------------
__global__ void head_kernel(const int* __restrict__ rt,
                            const float* __restrict__ hW,
                            const float* __restrict__ hb,
                            float* __restrict__ out) {
    int b = (blockIdx.x * blockDim.x + threadIdx.x) >> 5;
    int lane = threadIdx.x & 31;
    if (b >= BB) return;
    int r = rt[b];
    float acc = 0.f;
#pragma unroll
    for (int j = 0; j < NH; j++) {
        int c = j * HID + lane;
        acc = fmaf(g_pooled[b * HC + c], hW[r * HC + c], acc);
    }
#pragma unroll
    for (int off = 16; off; off >>= 1) acc += __shfl_xor_sync(0xffffffffu, acc, off);
    if (lane == 0) {
        float cnt = fmaxf(g_cnt[b], 1.f);
        out[b] = acc / cnt + hb[r];
    }
}

// ---------------- launch ----------------
extern "C" void kernel_launch(void* const* d_in, const int* in_sizes, int n_in,
                              void* d_out, int out_size) {
    const float* x     = (const float*)d_in[0];
    const int*   ei    = (const int*)d_in[1];
    const float* ea    = (const float*)d_in[2];
    const int*   batch = (const int*)d_in[3];
    const int*   rt    = (const int*)d_in[4];
    const float* Wq1 = (const float*)d_in[5];
    const float* bq1 = (const float*)d_in[6];
    const float* Wk1 = (const float*)d_in[7];
    const float* bk1 = (const float*)d_in[8];
    const float* Wv1 = (const float*)d_in[9];
    const float* bv1 = (const float*)d_in[10];
    const float* We1 = (const float*)d_in[11];
    const float* Ws1 = (const float*)d_in[12];
    const float* bs1 = (const float*)d_in[13];
    const float* Wq23 = (const float*)d_in[14];
    const float* bq23 = (const float*)d_in[15];
    const float* Wk23 = (const float*)d_in[16];
    const float* bk23 = (const float*)d_in[17];
    const float* Wv23 = (const float*)d_in[18];
    const float* bv23 = (const float*)d_in[19];
    const float* We23 = (const float*)d_in[20];
    const float* Ws23 = (const float*)d_in[21];
    const float* bs23 = (const float*)d_in[22];
    const float* headW = (const float*)d_in[23];
    const float* headb = (const float*)d_in[24];
    float* out = (float*)d_out;

    const int SMEM64  = (64 * 136 + 64 * 68) * 4;    // 52224 B
    const int SMEM128 = (128 * 136 + 64 * 132) * 4;  // 103424 B
    cudaFuncSetAttribute(gemm_tc_kernel<64, false>,
                         cudaFuncAttributeMaxDynamicSharedMemorySize, SMEM64);
    cudaFuncSetAttribute(gemm_tc_kernel<128, true>,
                         cudaFuncAttributeMaxDynamicSharedMemorySize, SMEM128);

    const dim3 gemm_grid(GEMM_GX, 4);
    const int node_blocks = (NN + 7) / 8;

    // ---- fork: first part of CSR build on side stream ----
    cudaEventRecord(g_evA, 0);
    cudaStreamWaitEvent(g_s2, g_evA, 0);
    zero_deg_kernel<<<256, 256, 0, g_s2>>>();       // kernel 1
    hist_kernel<<<1024, 256, 0, g_s2>>>(ei);        // kernel 2
    scanA_kernel<<<SCAN_B, SCAN_T, 0, g_s2>>>();    // kernel 3

    // ---- main stream: layer-1 GEMM enqueued 4th (profiled slot) ----
    gemm_tc_kernel<64, false><<<gemm_grid, 256, SMEM64>>>(
        x, Wq1, bq1, Wk1, bk1, Wv1, bv1, Ws1, bs1);

    // ---- rest of side-stream chain ----
    scanB_kernel<<<1, 256, 0, g_s2>>>();
    scanC_kernel<<<SCAN_B, SCAN_T, 0, g_s2>>>();
    bucket_kernel<<<1024, 256, 0, g_s2>>>(ei, ea);
    zero_pool_kernel<<<256, 256, 0, g_s2>>>();
    cnt_kernel<<<(NN + 255) / 256, 256, 0, g_s2>>>(batch);
    cudaEventRecord(g_evB, g_s2);

    cudaStreamWaitEvent(0, g_evB, 0);  // join before first edge pass
    node_edge_kernel<true, false><<<node_blocks, 256>>>(We1, batch);

    gemm_tc_kernel<128, true><<<gemm_grid, 256, SMEM128>>>(
        x, Wq23, bq23, Wk23, bk23, Wv23, bv23, Ws23, bs23);
    node_edge_kernel<true, false><<<node_blocks, 256>>>(We23, batch);

    gemm_tc_kernel<128, true><<<gemm_grid, 256, SMEM128>>>(
        x, Wq23 + HC * HC, bq23 + HC, Wk23 + HC * HC, bk23 + HC,
        Wv23 + HC * HC, bv23 + HC, Ws23 + HC * HC, bs23 + HC);
    node_edge_kernel<false, true><<<node_blocks, 256>>>(We23 + EDIM * HC, batch);

    head_kernel<<<(BB * 32 + 255) / 256, 256>>>(rt, headW, headb, out);
}

// round 16
// speedup vs baseline: 2.2311x; 1.0685x over previous
#include <cuda_runtime.h>
#include <cuda_bf16.h>
#include <cstdint>

#define NN 100000
#define EE 500000
#define BB 4096
#define HC 128
#define NH 4
#define HID 32
#define EDIM 4

#define SCAN_T 512
#define SCAN_B ((NN + SCAN_T - 1) / SCAN_T)  // 196

#define NTILES ((NN + 63) / 64)  // 1563
#define GEMM_GX 74               // 74*4 = 296 blocks = 2/SM, one wave

// ---------------- scratch (device globals: allocation-free) ----------------
__device__ __align__(16) __nv_bfloat16 g_qb[NN * HC];   // q bf16
__device__ __align__(16) __nv_bfloat16 g_kb[NN * HC];   // k bf16
__device__ __align__(16) __nv_bfloat16 g_vb[NN * HC];   // v bf16
__device__ float         g_s[NN * HC];    // skip (x@Ws + bs)
__device__ float         g_h[NN * HC];    // layer output / next-layer input
__device__ float         g_pooled[BB * HC];
__device__ float         g_cnt[BB];
// CSR build
__device__ int    g_deg[NN];
__device__ int    g_incl[NN];
__device__ int    g_rowptr[NN + 1];
__device__ int    g_cursor[NN];
__device__ int    g_bsum[SCAN_B];
__device__ int    g_boff[SCAN_B];
__device__ int    g_esrc[EE];
__device__ float4 g_eea[EE];

// ---------------- side stream for overlap ----------------
static cudaStream_t g_s2;
static cudaEvent_t g_evA, g_evB;
namespace {
struct StreamInit {
    StreamInit() {
        cudaStreamCreateWithFlags(&g_s2, cudaStreamNonBlocking);
        cudaEventCreateWithFlags(&g_evA, cudaEventDisableTiming);
        cudaEventCreateWithFlags(&g_evB, cudaEventDisableTiming);
    }
} g_stream_init;
}

// ---------------- helpers ----------------
__device__ __forceinline__ float to_tf32(float x) {
    uint32_t u;
    asm("cvt.rna.tf32.f32 %0, %1;" : "=r"(u) : "f"(x));
    return __uint_as_float(u);
}

__device__ __forceinline__ void mma_tf32(float& c0, float& c1, float& c2, float& c3,
                                         uint32_t a0, uint32_t a1, uint32_t a2, uint32_t a3,
                                         uint32_t b0, uint32_t b1) {
    asm volatile(
        "mma.sync.aligned.m16n8k8.row.col.f32.tf32.tf32.f32 "
        "{%0,%1,%2,%3}, {%4,%5,%6,%7}, {%8,%9}, {%0,%1,%2,%3};"
        : "+f"(c0), "+f"(c1), "+f"(c2), "+f"(c3)
        : "r"(a0), "r"(a1), "r"(a2), "r"(a3), "r"(b0), "r"(b1));
}

// ---------------- CSR build ----------------
__global__ void zero_deg_kernel() {
    int stride = gridDim.x * blockDim.x;
    for (int i = blockIdx.x * blockDim.x + threadIdx.x; i < NN; i += stride) g_deg[i] = 0;
}

__global__ void hist_kernel(const int* __restrict__ ei) {
    int stride = gridDim.x * blockDim.x;
    for (int e = blockIdx.x * blockDim.x + threadIdx.x; e < EE; e += stride)
        atomicAdd(&g_deg[ei[EE + e]], 1);
}

__global__ void scanA_kernel() {
    __shared__ int s[SCAN_T];
    int tid = threadIdx.x;
    int i = blockIdx.x * SCAN_T + tid;
    int v = (i < NN) ? g_deg[i] : 0;
    s[tid] = v;
    __syncthreads();
#pragma unroll
    for (int off = 1; off < SCAN_T; off <<= 1) {
        int t = (tid >= off) ? s[tid - off] : 0;
        __syncthreads();
        s[tid] += t;
        __syncthreads();
    }
    if (i < NN) g_incl[i] = s[tid];
    if (tid == SCAN_T - 1) g_bsum[blockIdx.x] = s[tid];
}

__global__ void scanB_kernel() {
    __shared__ int s[256];
    int tid = threadIdx.x;
    int v = (tid < SCAN_B) ? g_bsum[tid] : 0;
    s[tid] = v;
    __syncthreads();
#pragma unroll
    for (int off = 1; off < 256; off <<= 1) {
        int t = (tid >= off) ? s[tid - off] : 0;
        __syncthreads();
        s[tid] += t;
        __syncthreads();
    }
    if (tid < SCAN_B) g_boff[tid] = s[tid] - v;
}

__global__ void scanC_kernel() {
    int i = blockIdx.x * SCAN_T + threadIdx.x;
    if (i < NN) {
        int excl = g_incl[i] - g_deg[i] + g_boff[blockIdx.x];
        g_rowptr[i] = excl;
        g_cursor[i] = excl;
    }
    if (i == 0) g_rowptr[NN] = EE;
}

__global__ void bucket_kernel(const int* __restrict__ ei, const float* __restrict__ ea) {
    int stride = gridDim.x * blockDim.x;
    for (int e = blockIdx.x * blockDim.x + threadIdx.x; e < EE; e += stride) {
        int dst = ei[EE + e];
        int pos = atomicAdd(&g_cursor[dst], 1);
        g_esrc[pos] = ei[e];
        g_eea[pos] = reinterpret_cast<const float4*>(ea)[e];
    }
}

// ---------------- zero pool + count ----------------
__global__ void zero_pool_kernel() {
    int stride = gridDim.x * blockDim.x;
    int i0 = blockIdx.x * blockDim.x + threadIdx.x;
    for (int i = i0; i < BB * HC; i += stride) g_pooled[i] = 0.f;
    for (int i = i0; i < BB; i += stride) g_cnt[i] = 0.f;
}

__global__ void cnt_kernel(const int* __restrict__ batch) {
    int n = blockIdx.x * blockDim.x + threadIdx.x;
    if (n < NN) atomicAdd(&g_cnt[batch[n]], 1.f);
}

// ---------------- persistent W-resident tensor-core GEMM (R15 winner) ----------------
// q, k, v epilogues write bf16x2; s stays fp32.
template <int D, bool USE_H>
__global__ __launch_bounds__(256, 2) void gemm_tc_kernel(
    const float* __restrict__ x,
    const float* __restrict__ Wq, const float* __restrict__ bq,
    const float* __restrict__ Wk, const float* __restrict__ bk,
    const float* __restrict__ Wv, const float* __restrict__ bv,
    const float* __restrict__ Ws, const float* __restrict__ bs) {
    constexpr int XST = D + 4;
    constexpr int NXI = D / 16;
    extern __shared__ __align__(16) float smem_dyn[];
    float* ws = smem_dyn;           // [D][136]
    float* xs = smem_dyn + D * 136; // [64][XST]

    const float* xin = USE_H ? g_h : x;
    const float* W;
    const float* bias;
    int m = blockIdx.y;
    if (m == 0)      { W = Wq; bias = bq; }
    else if (m == 1) { W = Wk; bias = bk; }
    else if (m == 2) { W = Wv; bias = bv; }
    else             { W = Ws; bias = bs; }

    int tid = threadIdx.x;
    int lane = tid & 31, wid = tid >> 5;
    int warp_m = wid >> 2, warp_n = wid & 3;
    int gID = lane >> 2, t4 = lane & 3;

    for (int idx = tid; idx < D * 32; idx += 256) {
        int r = idx >> 5, cg = (idx & 31) * 4;
        float4 w = *(const float4*)&W[r * HC + cg];
        float* wp = &ws[r * 136 + cg];
        wp[0] = to_tf32(w.x); wp[1] = to_tf32(w.y);
        wp[2] = to_tf32(w.z); wp[3] = to_tf32(w.w);
    }

    float bia[4][2];
#pragma unroll
    for (int ni = 0; ni < 4; ni++) {
        int cb = warp_n * 32 + ni * 8 + 2 * t4;
        bia[ni][0] = bias[cb];
        bia[ni][1] = bias[cb + 1];
    }
    __syncthreads();

    __nv_bfloat16* bdst = (m == 0) ? g_qb : (m == 1) ? g_kb : g_vb;

    float4 xr[NXI];
    auto load_x = [&](int tl) {
#pragma unroll
        for (int t = 0; t < NXI; t++) {
            int idx = tid + t * 256;
            int row = idx / (D / 4);
            int cg = (idx % (D / 4)) * 4;
            int n = tl * 64 + row;
            xr[t] = (n < NN) ? *(const float4*)&xin[n * D + cg]
                             : make_float4(0.f, 0.f, 0.f, 0.f);
        }
    };

    int tile = blockIdx.x;
    if (tile < NTILES) load_x(tile);
    for (; tile < NTILES; tile += GEMM_GX) {
#pragma unroll
        for (int t = 0; t < NXI; t++) {
            int idx = tid + t * 256;
            int row = idx / (D / 4);
            int cg = (idx % (D / 4)) * 4;
            float* xp = &xs[row * XST + cg];
            xp[0] = to_tf32(xr[t].x); xp[1] = to_tf32(xr[t].y);
            xp[2] = to_tf32(xr[t].z); xp[3] = to_tf32(xr[t].w);
        }
        __syncthreads();
        int nxt = tile + GEMM_GX;
        if (nxt < NTILES) load_x(nxt);

        float acc[2][4][4];
#pragma unroll
        for (int mi = 0; mi < 2; mi++)
#pragma unroll
            for (int ni = 0; ni < 4; ni++)
#pragma unroll
                for (int r = 0; r < 4; r++) acc[mi][ni][r] = 0.f;

#pragma unroll
        for (int ks = 0; ks < D / 8; ks++) {
            int kk = ks * 8;
            uint32_t a[2][4], bf[4][2];
#pragma unroll
            for (int mi = 0; mi < 2; mi++) {
                int row = warp_m * 32 + mi * 16 + gID;
                a[mi][0] = __float_as_uint(xs[row * XST + kk + t4]);
                a[mi][1] = __float_as_uint(xs[(row + 8) * XST + kk + t4]);
                a[mi][2] = __float_as_uint(xs[row * XST + kk + t4 + 4]);
                a[mi][3] = __float_as_uint(xs[(row + 8) * XST + kk + t4 + 4]);
            }
#pragma unroll
            for (int ni = 0; ni < 4; ni++) {
                int col = warp_n * 32 + ni * 8 + gID;
                bf[ni][0] = __float_as_uint(ws[(kk + t4) * 136 + col]);
                bf[ni][1] = __float_as_uint(ws[(kk + t4 + 4) * 136 + col]);
            }
#pragma unroll
            for (int mi = 0; mi < 2; mi++)
#pragma unroll
                for (int ni = 0; ni < 4; ni++)
                    mma_tf32(acc[mi][ni][0], acc[mi][ni][1], acc[mi][ni][2], acc[mi][ni][3],
                             a[mi][0], a[mi][1], a[mi][2], a[mi][3],
                             bf[ni][0], bf[ni][1]);
        }
        __syncthreads();

        int node0 = tile * 64;
#pragma unroll
        for (int mi = 0; mi < 2; mi++) {
            int r0 = node0 + warp_m * 32 + mi * 16 + gID;
#pragma unroll
            for (int ni = 0; ni < 4; ni++) {
                int cb = warp_n * 32 + ni * 8 + 2 * t4;
                float v00 = acc[mi][ni][0] + bia[ni][0], v01 = acc[mi][ni][1] + bia[ni][1];
                float v10 = acc[mi][ni][2] + bia[ni][0], v11 = acc[mi][ni][3] + bia[ni][1];
                if (m == 3) {
                    if (r0 < NN)     { g_s[r0 * HC + cb] = v00; g_s[r0 * HC + cb + 1] = v01; }
                    if (r0 + 8 < NN) { g_s[(r0 + 8) * HC + cb] = v10; g_s[(r0 + 8) * HC + cb + 1] = v11; }
                } else {
                    if (r0 < NN) {
                        __nv_bfloat162 p;
                        p.x = __float2bfloat16(v00); p.y = __float2bfloat16(v01);
                        *reinterpret_cast<__nv_bfloat162*>(&bdst[r0 * HC + cb]) = p;
                    }
                    if (r0 + 8 < NN) {
                        __nv_bfloat162 p;
                        p.x = __float2bfloat16(v10); p.y = __float2bfloat16(v11);
                        *reinterpret_cast<__nv_bfloat162*>(&bdst[(r0 + 8) * HC + cb]) = p;
                    }
                }
            }
        }
    }
}

// ---------------- per-node fused edge pass v3 (rank-4 e-factorization) ----------------
// logit = q·k + ea·t where t[d] = We[d,:]·q (per node, 4 vals); the message's
// e-contribution is deferred: Sum(alpha*e) = (Sum(alpha*ea)) @ We applied once
// after the loop. Inner loop per edge: 8 FMA + 3 shfl + exp (was ~28 FMA).
template <bool RELU, bool POOL>
__global__ __launch_bounds__(256) void node_edge_kernel(const float* __restrict__ We,
                                                        const int* __restrict__ batch) {
    __shared__ float Wes[EDIM * HC];
    for (int i = threadIdx.x; i < EDIM * HC; i += blockDim.x) Wes[i] = We[i];
    __syncthreads();

    int n = blockIdx.x * 8 + (threadIdx.x >> 5);
    int lane = threadIdx.x & 31;
    if (n >= NN) return;

    int c0 = lane * 4;  // head = lane>>3; 4 consecutive columns per lane

    float Wreg[EDIM][4];
#pragma unroll
    for (int d = 0; d < EDIM; d++) {
        float4 w = *reinterpret_cast<const float4*>(&Wes[d * HC + c0]);
        Wreg[d][0] = w.x; Wreg[d][1] = w.y; Wreg[d][2] = w.z; Wreg[d][3] = w.w;
    }

    auto unpack = [](uint2 r, float* out) {
        float2 lo = __bfloat1622float2(*reinterpret_cast<__nv_bfloat162*>(&r.x));
        float2 hi = __bfloat1622float2(*reinterpret_cast<__nv_bfloat162*>(&r.y));
        out[0] = lo.x; out[1] = lo.y; out[2] = hi.x; out[3] = hi.y;
    };

    uint2 qr = *reinterpret_cast<const uint2*>(&g_qb[n * HC + c0]);
    float qv[4];
    unpack(qr, qv);

    // t[d] = We[d, head cols] . q (reduced over the 8-lane head group)
    float t[EDIM];
#pragma unroll
    for (int d = 0; d < EDIM; d++) {
        t[d] = qv[0] * Wreg[d][0] + qv[1] * Wreg[d][1] + qv[2] * Wreg[d][2] + qv[3] * Wreg[d][3];
    }
#pragma unroll
    for (int off = 4; off; off >>= 1) {
#pragma unroll
        for (int d = 0; d < EDIM; d++) t[d] += __shfl_xor_sync(0xffffffffu, t[d], off);
    }

    float acc[4] = {0.f, 0.f, 0.f, 0.f};
    float4 aea = make_float4(0.f, 0.f, 0.f, 0.f);
    float asum = 0.f;

    int r0 = g_rowptr[n];
    int r1 = g_rowptr[n + 1];

    int i = r0;
    for (; i + 1 < r1; i += 2) {
        int s0 = g_esrc[i], s1 = g_esrc[i + 1];
        float4 a0 = g_eea[i], a1 = g_eea[i + 1];
        uint2 kr0 = *reinterpret_cast<const uint2*>(&g_kb[s0 * HC + c0]);
        uint2 vr0 = *reinterpret_cast<const uint2*>(&g_vb[s0 * HC + c0]);
        uint2 kr1 = *reinterpret_cast<const uint2*>(&g_kb[s1 * HC + c0]);
        uint2 vr1 = *reinterpret_cast<const uint2*>(&g_vb[s1 * HC + c0]);
        float k0[4], v0[4], k1[4], v1[4];
        unpack(kr0, k0); unpack(vr0, v0);
        unpack(kr1, k1); unpack(vr1, v1);

        float p0 = 0.f, p1 = 0.f;
#pragma unroll
        for (int u = 0; u < 4; u++) {
            p0 = fmaf(qv[u], k0[u], p0);
            p1 = fmaf(qv[u], k1[u], p1);
        }
#pragma unroll
        for (int off = 4; off; off >>= 1) {
            p0 += __shfl_xor_sync(0xffffffffu, p0, off);
            p1 += __shfl_xor_sync(0xffffffffu, p1, off);
        }
        p0 += a0.x * t[0] + a0.y * t[1] + a0.z * t[2] + a0.w * t[3];
        p1 += a1.x * t[0] + a1.y * t[1] + a1.z * t[2] + a1.w * t[3];
        float al0 = __expf(p0 * 0.17677669529663687f);  // 1/sqrt(32)
        float al1 = __expf(p1 * 0.17677669529663687f);
        asum += al0 + al1;
#pragma unroll
        for (int u = 0; u < 4; u++) {
            acc[u] = fmaf(al0, v0[u], acc[u]);
            acc[u] = fmaf(al1, v1[u], acc[u]);
        }
        aea.x = fmaf(al0, a0.x, fmaf(al1, a1.x, aea.x));
        aea.y = fmaf(al0, a0.y, fmaf(al1, a1.y, aea.y));
        aea.z = fmaf(al0, a0.z, fmaf(al1, a1.z, aea.z));
        aea.w = fmaf(al0, a0.w, fmaf(al1, a1.w, aea.w));
    }
    if (i < r1) {
        int s0 = g_esrc[i];
        float4 a0 = g_eea[i];
        uint2 kr0 = *reinterpret_cast<const uint2*>(&g_kb[s0 * HC + c0]);
        uint2 vr0 = *reinterpret_cast<const uint2*>(&g_vb[s0 * HC + c0]);
        float k0[4], v0[4];
        unpack(kr0, k0); unpack(vr0, v0);
        float p0 = 0.f;
#pragma unroll
        for (int u = 0; u < 4; u++) p0 = fmaf(qv[u], k0[u], p0);
#pragma unroll
        for (int off = 4; off; off >>= 1) p0 += __shfl_xor_sync(0xffffffffu, p0, off);
        p0 += a0.x * t[0] + a0.y * t[1] + a0.z * t[2] + a0.w * t[3];
        float al0 = __expf(p0 * 0.17677669529663687f);
        asum += al0;
#pragma unroll
        for (int u = 0; u < 4; u++) acc[u] = fmaf(al0, v0[u], acc[u]);
        aea.x = fmaf(al0, a0.x, aea.x);
        aea.y = fmaf(al0, a0.y, aea.y);
        aea.z = fmaf(al0, a0.z, aea.z);
        aea.w = fmaf(al0, a0.w, aea.w);
    }

    float inv = 1.f / (asum + 1e-16f);
    float4 s4 = *reinterpret_cast<const float4*>(&g_s[n * HC + c0]);
    float h[4];
#pragma unroll
    for (int u = 0; u < 4; u++) {
        float e_acc = aea.x * Wreg[0][u] + aea.y * Wreg[1][u] + aea.z * Wreg[2][u] + aea.w * Wreg[3][u];
        h[u] = (acc[u] + e_acc) * inv;
    }
    h[0] += s4.x; h[1] += s4.y; h[2] += s4.z; h[3] += s4.w;
    if (RELU) {
#pragma unroll
        for (int u = 0; u < 4; u++) h[u] = fmaxf(h[u], 0.f);
    }
    if (POOL) {
        int b = batch[n];
        atomicAdd(&g_pooled[b * HC + c0 + 0], h[0]);
        atomicAdd(&g_pooled[b * HC + c0 + 1], h[1]);
        atomicAdd(&g_pooled[b * HC + c0 + 2], h[2]);
        atomicAdd(&g_pooled[b * HC + c0 + 3], h[3]);
    } else {
        *reinterpret_cast<float4*>(&g_h[n * HC + c0]) = make_float4(h[0], h[1], h[2], h[3]);
    }
}

// ---------------- head ----------------
__global__ void head_kernel(const int* __restrict__ rt,
                            const float* __restrict__ hW,
                            const float* __restrict__ hb,
                            float* __restrict__ out) {
    int b = (blockIdx.x * blockDim.x + threadIdx.x) >> 5;
    int lane = threadIdx.x & 31;
    if (b >= BB) return;
    int r = rt[b];
    float acc = 0.f;
#pragma unroll
    for (int j = 0; j < NH; j++) {
        int c = j * HID + lane;
        acc = fmaf(g_pooled[b * HC + c], hW[r * HC + c], acc);
    }
#pragma unroll
    for (int off = 16; off; off >>= 1) acc += __shfl_xor_sync(0xffffffffu, acc, off);
    if (lane == 0) {
        float cnt = fmaxf(g_cnt[b], 1.f);
        out[b] = acc / cnt + hb[r];
    }
}

// ---------------- launch ----------------
extern "C" void kernel_launch(void* const* d_in, const int* in_sizes, int n_in,
                              void* d_out, int out_size) {
    const float* x     = (const float*)d_in[0];
    const int*   ei    = (const int*)d_in[1];
    const float* ea    = (const float*)d_in[2];
    const int*   batch = (const int*)d_in[3];
    const int*   rt    = (const int*)d_in[4];
    const float* Wq1 = (const float*)d_in[5];
    const float* bq1 = (const float*)d_in[6];
    const float* Wk1 = (const float*)d_in[7];
    const float* bk1 = (const float*)d_in[8];
    const float* Wv1 = (const float*)d_in[9];
    const float* bv1 = (const float*)d_in[10];
    const float* We1 = (const float*)d_in[11];
    const float* Ws1 = (const float*)d_in[12];
    const float* bs1 = (const float*)d_in[13];
    const float* Wq23 = (const float*)d_in[14];
    const float* bq23 = (const float*)d_in[15];
    const float* Wk23 = (const float*)d_in[16];
    const float* bk23 = (const float*)d_in[17];
    const float* Wv23 = (const float*)d_in[18];
    const float* bv23 = (const float*)d_in[19];
    const float* We23 = (const float*)d_in[20];
    const float* Ws23 = (const float*)d_in[21];
    const float* bs23 = (const float*)d_in[22];
    const float* headW = (const float*)d_in[23];
    const float* headb = (const float*)d_in[24];
    float* out = (float*)d_out;

    const int SMEM64  = (64 * 136 + 64 * 68) * 4;    // 52224 B
    const int SMEM128 = (128 * 136 + 64 * 132) * 4;  // 103424 B
    cudaFuncSetAttribute(gemm_tc_kernel<64, false>,
                         cudaFuncAttributeMaxDynamicSharedMemorySize, SMEM64);
    cudaFuncSetAttribute(gemm_tc_kernel<128, true>,
                         cudaFuncAttributeMaxDynamicSharedMemorySize, SMEM128);

    const dim3 gemm_grid(GEMM_GX, 4);
    const int node_blocks = (NN + 7) / 8;

    // ---- fork: first part of CSR build on side stream ----
    cudaEventRecord(g_evA, 0);
    cudaStreamWaitEvent(g_s2, g_evA, 0);
    zero_deg_kernel<<<256, 256, 0, g_s2>>>();       // kernel 1
    hist_kernel<<<1024, 256, 0, g_s2>>>(ei);        // kernel 2
    scanA_kernel<<<SCAN_B, SCAN_T, 0, g_s2>>>();    // kernel 3

    // ---- main stream: layer-1 GEMM enqueued 4th (profiled slot) ----
    gemm_tc_kernel<64, false><<<gemm_grid, 256, SMEM64>>>(
        x, Wq1, bq1, Wk1, bk1, Wv1, bv1, Ws1, bs1);

    // ---- rest of side-stream chain ----
    scanB_kernel<<<1, 256, 0, g_s2>>>();
    scanC_kernel<<<SCAN_B, SCAN_T, 0, g_s2>>>();
    bucket_kernel<<<1024, 256, 0, g_s2>>>(ei, ea);
    zero_pool_kernel<<<256, 256, 0, g_s2>>>();
    cnt_kernel<<<(NN + 255) / 256, 256, 0, g_s2>>>(batch);
    cudaEventRecord(g_evB, g_s2);

    cudaStreamWaitEvent(0, g_evB, 0);  // join before first edge pass
    node_edge_kernel<true, false><<<node_blocks, 256>>>(We1, batch);

    gemm_tc_kernel<128, true><<<gemm_grid, 256, SMEM128>>>(
        x, Wq23, bq23, Wk23, bk23, Wv23, bv23, Ws23, bs23);
    node_edge_kernel<true, false><<<node_blocks, 256>>>(We23, batch);

    gemm_tc_kernel<128, true><<<gemm_grid, 256, SMEM128>>>(
        x, Wq23 + HC * HC, bq23 + HC, Wk23 + HC * HC, bk23 + HC,
        Wv23 + HC * HC, bv23 + HC, Ws23 + HC * HC, bs23 + HC);
    node_edge_kernel<false, true><<<node_blocks, 256>>>(We23 + EDIM * HC, batch);

    head_kernel<<<(BB * 32 + 255) / 256, 256>>>(rt, headW, headb, out);
}